// round 14
// baseline (speedup 1.0000x reference)
#include <cuda_runtime.h>
#include <cuda_fp16.h>
#include <math.h>
#include <stdint.h>

// ---------------------------------------------------------------------------
// Problem constants
// ---------------------------------------------------------------------------
constexpr int Bb   = 2;
constexpr int Cc   = 96;
constexpr int HEADS= 6;
constexpr int TOK  = Bb * 256 * 256;          // 131072 tokens

// ---------------------------------------------------------------------------
// Static device scratch
// ---------------------------------------------------------------------------
__device__ float g_y   [TOK * Cc];            // fp32 residual carrier
__device__ float g_x2  [TOK * Cc];

__device__ __half g_qkvx16[TOK * 288];
__device__ __half g_qkvr16[TOK * 288];
__device__ __half g_ln16 [TOK * 96];
__device__ __half g_lnr16[TOK * 96];
__device__ __half g_y16  [TOK * 96];
__device__ __half g_t16  [TOK * 96];
__device__ __half g_h16  [TOK * 192];
__device__ __half g_h16b [TOK * 192];

__device__ __half g_qkvw16[288 * 96];
__device__ __half g_projw16[96 * 96];
__device__ __half g_fc1w16[192 * 96];
__device__ __half g_fc2w16[96 * 192];
__device__ __half g_trunkw16[36 * 96 * 96];   // [layer*9+tap][co][ci]
__device__ __half g_convmw16[9 * 192 * 192];  // [tap][co][ci]

#define DEV __device__ __forceinline__

DEV float gelu_f(float v) { return 0.5f * v * (1.0f + erff(v * 0.70710678118654752f)); }

// D += A(16x16, f16, row) * B(16x8, f16, col), fp32 accum
DEV void mma_f16(float* c, const unsigned* a, const unsigned* b) {
    asm("mma.sync.aligned.m16n8k16.row.col.f32.f16.f16.f32 "
        "{%0,%1,%2,%3}, {%4,%5,%6,%7}, {%8,%9}, {%0,%1,%2,%3};"
        : "+f"(c[0]), "+f"(c[1]), "+f"(c[2]), "+f"(c[3])
        : "r"(a[0]), "r"(a[1]), "r"(a[2]), "r"(a[3]), "r"(b[0]), "r"(b[1]));
}

DEV unsigned sa(const void* p) { return (unsigned)__cvta_generic_to_shared(p); }

DEV void cpa16(unsigned dst, const void* src) {
    asm volatile("cp.async.cg.shared.global [%0], [%1], 16;"
                 :: "r"(dst), "l"(__cvta_generic_to_global(src)));
}
DEV void cpa_commit_wait() {
    asm volatile("cp.async.commit_group;");
    asm volatile("cp.async.wait_group 0;" ::: "memory");
}

// 16 consecutive halves -> 4 float4
DEV void ldh16(const __half* p, float4* o) {
    uint4 u = *(const uint4*)p;
    uint4 v = *(const uint4*)(p + 8);
    const __half2* h0 = (const __half2*)&u;
    const __half2* h1 = (const __half2*)&v;
    float2 a0 = __half22float2(h0[0]), a1 = __half22float2(h0[1]);
    float2 a2 = __half22float2(h0[2]), a3 = __half22float2(h0[3]);
    float2 b0 = __half22float2(h1[0]), b1 = __half22float2(h1[1]);
    float2 b2 = __half22float2(h1[2]), b3 = __half22float2(h1[3]);
    o[0] = make_float4(a0.x, a0.y, a1.x, a1.y);
    o[1] = make_float4(a2.x, a2.y, a3.x, a3.y);
    o[2] = make_float4(b0.x, b0.y, b1.x, b1.y);
    o[3] = make_float4(b2.x, b2.y, b3.x, b3.y);
}

// ---------------------------------------------------------------------------
// Weight conversion kernels
// ---------------------------------------------------------------------------
__global__ void tohalf_k(const float* __restrict__ src, __half* __restrict__ dst, int n)
{
    int i = blockIdx.x * 256 + threadIdx.x;
    if (i < n) dst[i] = __float2half_rn(src[i]);
}

// fp32 [tap][ci][co] -> fp16 [tap][co][ci]
__global__ void tohalfT_k(const float* __restrict__ src, __half* __restrict__ dst,
                          int CI, int CO, int ntap)
{
    int i = blockIdx.x * 256 + threadIdx.x;
    if (i >= ntap * CI * CO) return;
    int ci = i % CI, co = (i / CI) % CO, tap = i / (CI * CO);
    dst[i] = __float2half_rn(src[((size_t)tap * CI + ci) * CO + co]);
}

// ---------------------------------------------------------------------------
// LayerNorm: single and fused-dual variants; fp16 output
// ---------------------------------------------------------------------------
DEV void ln_body(const float* src, const float* g, const float* bt, __half* dst, int lane)
{
    float v0 = src[lane], v1 = src[lane + 32], v2 = src[lane + 64];
    float s = v0 + v1 + v2;
    #pragma unroll
    for (int o = 16; o > 0; o >>= 1) s += __shfl_xor_sync(0xffffffffu, s, o);
    float mu = s * (1.0f / 96.0f);
    float d0 = v0 - mu, d1 = v1 - mu, d2 = v2 - mu;
    float sq = d0 * d0 + d1 * d1 + d2 * d2;
    #pragma unroll
    for (int o = 16; o > 0; o >>= 1) sq += __shfl_xor_sync(0xffffffffu, sq, o);
    float inv = rsqrtf(sq * (1.0f / 96.0f) + 1e-5f);
    dst[lane]      = __float2half_rn(d0 * inv * g[lane]      + bt[lane]);
    dst[lane + 32] = __float2half_rn(d1 * inv * g[lane + 32] + bt[lane + 32]);
    dst[lane + 64] = __float2half_rn(d2 * inv * g[lane + 64] + bt[lane + 64]);
}

__global__ void ln_kernel(const float* __restrict__ in, const float* __restrict__ g,
                          const float* __restrict__ bt, __half* __restrict__ out, int shift)
{
    int gid  = blockIdx.x * blockDim.x + threadIdx.x;
    int tok  = gid >> 5;
    int lane = gid & 31;
    if (tok >= TOK) return;
    int b = tok >> 16, rr = tok & 65535, h = rr >> 8, w = rr & 255;
    const float* src = in + (size_t)((b << 16) | (((h + shift) & 255) << 8) | ((w + shift) & 255)) * 96;
    ln_body(src, g, bt, out + (size_t)tok * 96, lane);
}

__global__ void ln2_kernel(const float* __restrict__ in0, const float* __restrict__ in1,
                           const float* __restrict__ g, const float* __restrict__ bt,
                           __half* __restrict__ out0, __half* __restrict__ out1)
{
    int half = gridDim.x >> 1;
    int bid = blockIdx.x;
    const float* in = (bid < half) ? in0 : in1;
    __half* out = (bid < half) ? out0 : out1;
    int bb = (bid < half) ? bid : bid - half;
    int gid = bb * blockDim.x + threadIdx.x;
    int tok = gid >> 5, lane = gid & 31;
    if (tok >= TOK) return;
    int b = tok >> 16, rr = tok & 65535, h = rr >> 8, w = rr & 255;
    const float* src = in + (size_t)((b << 16) | (((h + 4) & 255) << 8) | ((w + 4) & 255)) * 96;
    ln_body(src, g, bt, out + (size_t)tok * 96, lane);
}

// ---------------------------------------------------------------------------
// Tensor-core GEMM (fp16 m16n8k16), cp.async staging from fp16 mirrors.
// Block: 128 rows x 96 cols, 8 warps (4 Mquad x 2 Nhalf); warp 2x6 frags.
// Fused input select: blockIdx.y < split -> (Ax, o16x, n0 = y*96)
//                     else              -> (Ar, o16r, n0 = (y-split+1)*96)
// MODE 1 proj roll+res fp32, 2 res fp32, 3 fp16 plain. ACT 0 none, 1 gelu.
// ---------------------------------------------------------------------------
template<int K, int ACT, int MODE>
__global__ void __launch_bounds__(256) gemm_h(
        const __half* __restrict__ Ax, const __half* __restrict__ Ar,
        const __half* __restrict__ W, const float* __restrict__ bias,
        const float* __restrict__ res, float* __restrict__ out32,
        __half* __restrict__ o16x, __half* __restrict__ o16r,
        int outN, int split)
{
    constexpr int KP = K / 2;
    constexpr int AP = KP + 4;                  // 52 or 100
    constexpr int CH = K / 8;
    extern __shared__ unsigned smem_u[];
    unsigned* As = smem_u;
    unsigned* Ws = smem_u + 128 * AP;

    int y = blockIdx.y;
    const __half* A; __half* o16; int n0;
    if (y < split) { A = Ax; o16 = o16x; n0 = y * 96; }
    else           { A = Ar; o16 = o16r; n0 = (y - split + 1) * 96; }

    int m0 = blockIdx.x * 128;
    int t  = threadIdx.x;
    int warp = t >> 5, lane = t & 31;
    int wm = warp >> 1, wn = warp & 1;
    int g = lane >> 2, tg = lane & 3;

    unsigned as_base = sa(As), ws_base = sa(Ws);
    #pragma unroll
    for (int i = 0; i < 128 * CH / 256; i++) {
        int idx = t + i * 256;
        int m = idx / CH, c = idx % CH;
        cpa16(as_base + (unsigned)(m * AP + c * 4) * 4, A + (size_t)(m0 + m) * K + c * 8);
    }
    for (int idx = t; idx < 96 * CH; idx += 256) {
        int c = idx / CH, ck = idx % CH;
        cpa16(ws_base + (unsigned)(c * AP + ck * 4) * 4, W + (size_t)(n0 + c) * K + ck * 8);
    }
    cpa_commit_wait();
    __syncthreads();

    float acc[2][6][4];
    #pragma unroll
    for (int i = 0; i < 2; i++)
        #pragma unroll
        for (int j = 0; j < 6; j++)
            #pragma unroll
            for (int q = 0; q < 4; q++) acc[i][j][q] = 0.0f;

    #pragma unroll
    for (int s = 0; s < K / 16; s++) {
        int kb = s * 8;
        unsigned a[2][4];
        #pragma unroll
        for (int i = 0; i < 2; i++) {
            int mb = (wm * 2 + i) * 16;
            a[i][0] = As[(mb + g)     * AP + kb + tg];
            a[i][1] = As[(mb + g + 8) * AP + kb + tg];
            a[i][2] = As[(mb + g)     * AP + kb + tg + 4];
            a[i][3] = As[(mb + g + 8) * AP + kb + tg + 4];
        }
        unsigned b[6][2];
        #pragma unroll
        for (int j = 0; j < 6; j++) {
            int col = wn * 48 + j * 8 + g;
            b[j][0] = Ws[col * AP + kb + tg];
            b[j][1] = Ws[col * AP + kb + tg + 4];
        }
        #pragma unroll
        for (int i = 0; i < 2; i++)
            #pragma unroll
            for (int j = 0; j < 6; j++) mma_f16(acc[i][j], a[i], b[j]);
    }

    #pragma unroll
    for (int i = 0; i < 2; i++) {
        int rb = m0 + (wm * 2 + i) * 16;
        #pragma unroll
        for (int j = 0; j < 6; j++) {
            int c = wn * 48 + j * 8 + tg * 2;
            #pragma unroll
            for (int half = 0; half < 2; half++) {
                int row = rb + g + half * 8;
                float v0 = acc[i][j][half * 2]     + bias[n0 + c];
                float v1 = acc[i][j][half * 2 + 1] + bias[n0 + c + 1];
                if (ACT == 1) { v0 = gelu_f(v0); v1 = gelu_f(v1); }
                if (MODE == 1) {
                    int bb = row >> 16, rr = row & 65535, hy = rr >> 8, wx = rr & 255;
                    int tr = (bb << 16) | (((hy + 4) & 255) << 8) | ((wx + 4) & 255);
                    out32[(size_t)tr * 96 + c]     = res[(size_t)tr * 96 + c]     + v0;
                    out32[(size_t)tr * 96 + c + 1] = res[(size_t)tr * 96 + c + 1] + v1;
                } else if (MODE == 2) {
                    out32[(size_t)row * 96 + c]     = res[(size_t)row * 96 + c]     + v0;
                    out32[(size_t)row * 96 + c + 1] = res[(size_t)row * 96 + c + 1] + v1;
                } else {
                    *(__half2*)&o16[(size_t)row * outN + n0 + c] =
                        __floats2half2_rn(v0, v1);
                }
            }
        }
    }
}

// ---------------------------------------------------------------------------
// Tensor-core 3x3 SAME conv (implicit GEMM, fp16 m16n8k16), cp.async staging.
// Block: 16x16 pixel tile x 48 couts, 256 threads (8 warps: 4 Mquad x 2 Nhalf,
// each Nhalf = 24 cols = 3 n-frags). Smem 60.5 KB => 3 CTAs/SM.
// grid = (16, 16, b*(COUT/48) + coq). ACT 0/1/2 = none/relu/gelu.
// ---------------------------------------------------------------------------
template<int CIN, int COUT, int ACT, int RES, int O32, int O16>
__global__ void __launch_bounds__(256, 3) conv_h(
        const __half* __restrict__ in16, const __half* __restrict__ w16t,
        const float* __restrict__ bias, const float* __restrict__ res,
        float* __restrict__ out32, __half* __restrict__ out16)
{
    constexpr int PIT = 20;           // kpair pitch (u32), %32 = 20
    constexpr int NH = COUT / 48;
    extern __shared__ unsigned smem_u[];
    unsigned* ws_u  = smem_u;                       // [9*48][PIT]
    unsigned* ins_u = smem_u + 9 * 48 * PIT;        // [324][PIT]

    int x0 = blockIdx.x * 16, y0 = blockIdx.y * 16;
    int zb = blockIdx.z;
    int coq = zb % NH;
    int b   = zb / NH;
    int t  = threadIdx.x;
    int warp = t >> 5, lane = t & 31;
    int wm = warp >> 1, wn = warp & 1;
    int g = lane >> 2, tg = lane & 3;

    unsigned ins_base = sa(ins_u), ws_base = sa(ws_u);

    float acc[4][3][4];
    #pragma unroll
    for (int i = 0; i < 4; i++)
        #pragma unroll
        for (int j = 0; j < 3; j++)
            #pragma unroll
            for (int q = 0; q < 4; q++) acc[i][j][q] = 0.0f;

    for (int ci0 = 0; ci0 < CIN; ci0 += 32) {
        // halo 18x18, 32 ci = 4 x 16B per pixel
        for (int idx = t; idx < 324 * 4; idx += 256) {
            int ck = idx & 3, pos = idx >> 2;
            int hp = pos / 18, wp = pos % 18;
            int gy = y0 + hp - 1, gx = x0 + wp - 1;
            unsigned dst = ins_base + (unsigned)(pos * PIT + ck * 4) * 4;
            if ((unsigned)gy < 256u && (unsigned)gx < 256u) {
                cpa16(dst, in16 + (size_t)((b << 16) | (gy << 8) | gx) * CIN + ci0 + ck * 8);
            } else {
                *(uint4*)&ins_u[pos * PIT + ck * 4] = make_uint4(0, 0, 0, 0);
            }
        }
        // weights: 9 taps x 48 co, 32 ci = 4 x 16B per row
        for (int idx = t; idx < 9 * 48 * 4; idx += 256) {
            int ck = idx & 3, row = idx >> 2;       // row = tap*48 + co
            int tap = row / 48, co = row % 48;
            cpa16(ws_base + (unsigned)(row * PIT + ck * 4) * 4,
                  w16t + ((size_t)tap * COUT + coq * 48 + co) * CIN + ci0 + ck * 8);
        }
        cpa_commit_wait();
        __syncthreads();

        #pragma unroll
        for (int dy = 0; dy < 3; dy++) {
            #pragma unroll
            for (int dx = 0; dx < 3; dx++) {
                const unsigned* wt = ws_u + (dy * 3 + dx) * 48 * PIT;
                #pragma unroll
                for (int s = 0; s < 2; s++) {
                    int cb = s * 8;
                    unsigned a[4][4];
                    #pragma unroll
                    for (int i = 0; i < 4; i++) {
                        int base = (wm * 4 + i + dy) * 18 + dx;
                        a[i][0] = ins_u[(base + g)     * PIT + cb + tg];
                        a[i][1] = ins_u[(base + g + 8) * PIT + cb + tg];
                        a[i][2] = ins_u[(base + g)     * PIT + cb + tg + 4];
                        a[i][3] = ins_u[(base + g + 8) * PIT + cb + tg + 4];
                    }
                    unsigned bfr[3][2];
                    #pragma unroll
                    for (int j = 0; j < 3; j++) {
                        int col = wn * 24 + j * 8 + g;
                        bfr[j][0] = wt[col * PIT + cb + tg];
                        bfr[j][1] = wt[col * PIT + cb + tg + 4];
                    }
                    #pragma unroll
                    for (int i = 0; i < 4; i++)
                        #pragma unroll
                        for (int j = 0; j < 3; j++) mma_f16(acc[i][j], a[i], bfr[j]);
                }
            }
        }
        __syncthreads();
    }

    #pragma unroll
    for (int i = 0; i < 4; i++) {
        int y = y0 + wm * 4 + i;
        #pragma unroll
        for (int j = 0; j < 3; j++) {
            int co = coq * 48 + wn * 24 + j * 8 + tg * 2;
            float b0 = bias[co], b1 = bias[co + 1];
            #pragma unroll
            for (int half = 0; half < 2; half++) {
                int x = x0 + g + half * 8;
                size_t base = (size_t)((b << 16) | (y << 8) | x) * COUT + co;
                float v0 = acc[i][j][half * 2]     + b0;
                float v1 = acc[i][j][half * 2 + 1] + b1;
                if (ACT == 1) { v0 = fmaxf(v0, 0.0f); v1 = fmaxf(v1, 0.0f); }
                if (ACT == 2) { v0 = gelu_f(v0); v1 = gelu_f(v1); }
                if (RES) { v0 += res[base]; v1 += res[base + 1]; }
                if (O32) { out32[base] = v0; out32[base + 1] = v1; }
                if (O16) *(__half2*)&out16[base] = __floats2half2_rn(v0, v1);
            }
        }
    }
}

// ---------------------------------------------------------------------------
// Windowed dual attention. One block per (window, head). 64 threads = rows.
// ---------------------------------------------------------------------------
DEV int regio(int wblk, int i) { return (wblk < 31) ? 0 : ((i < 4) ? 1 : 2); }

DEV void attn_pass(const float4 (*K4)[4], const float4 (*V4)[4], const float4 q[4],
                   float lsv, const float* rpb_s, int i1, int j1, int cnt1,
                   int wh, int ww, float4 o[4])
{
    float s[64];
    #pragma unroll
    for (int m = 0; m < 64; m++) {
        const float4* kr = K4[m];
        float d;
        d  = q[0].x * kr[0].x + q[0].y * kr[0].y + q[0].z * kr[0].z + q[0].w * kr[0].w;
        d += q[1].x * kr[1].x + q[1].y * kr[1].y + q[1].z * kr[1].z + q[1].w * kr[1].w;
        d += q[2].x * kr[2].x + q[2].y * kr[2].y + q[2].z * kr[2].z + q[2].w * kr[2].w;
        d += q[3].x * kr[3].x + q[3].y * kr[3].y + q[3].z * kr[3].z + q[3].w * kr[3].w;
        int i2 = m >> 3, j2 = m & 7;
        float rb = rpb_s[(i1 - i2 + 7) * 15 + (j1 - j2 + 7)];
        int cnt2 = regio(wh, i2) * 3 + regio(ww, j2);
        s[m] = d * lsv + rb + ((cnt1 != cnt2) ? -100.0f : 0.0f);
    }
    float mx = s[0];
    #pragma unroll
    for (int m = 1; m < 64; m++) mx = fmaxf(mx, s[m]);
    float sum = 0.0f;
    float4 a0 = make_float4(0, 0, 0, 0), a1 = a0, a2 = a0, a3 = a0;
    #pragma unroll
    for (int m = 0; m < 64; m++) {
        float p = expf(s[m] - mx);
        sum += p;
        const float4* vr = V4[m];
        a0.x += p * vr[0].x; a0.y += p * vr[0].y; a0.z += p * vr[0].z; a0.w += p * vr[0].w;
        a1.x += p * vr[1].x; a1.y += p * vr[1].y; a1.z += p * vr[1].z; a1.w += p * vr[1].w;
        a2.x += p * vr[2].x; a2.y += p * vr[2].y; a2.z += p * vr[2].z; a2.w += p * vr[2].w;
        a3.x += p * vr[3].x; a3.y += p * vr[3].y; a3.z += p * vr[3].z; a3.w += p * vr[3].w;
    }
    float inv = 1.0f / sum;
    o[0] = make_float4(a0.x * inv, a0.y * inv, a0.z * inv, a0.w * inv);
    o[1] = make_float4(a1.x * inv, a1.y * inv, a1.z * inv, a1.w * inv);
    o[2] = make_float4(a2.x * inv, a2.y * inv, a2.z * inv, a2.w * inv);
    o[3] = make_float4(a3.x * inv, a3.y * inv, a3.z * inv, a3.w * inv);
}

__global__ void attn_kernel(const __half* __restrict__ qkvx, const __half* __restrict__ qkvr,
                            const float* __restrict__ lsp, const float* __restrict__ gat,
                            const float* __restrict__ rpbt, float* __restrict__ out,
                            __half* __restrict__ out16)
{
    __shared__ float4 ks[64][4], vs[64][4], krs[64][4], vrs[64][4];
    __shared__ float rpb_s[225];
    int blk  = blockIdx.x;
    int head = blk % HEADS;
    int widx = blk / HEADS;
    int b  = widx >> 10;
    int nw = widx & 1023;
    int wh = nw >> 5, ww = nw & 31;
    int n  = threadIdx.x;
    int i1 = n >> 3, j1 = n & 7;

    size_t tok = (size_t)((b << 16) | ((wh * 8 + i1) << 8) | (ww * 8 + j1));
    size_t rowbase = tok * 288 + head * 16;

    float4 q[4];
    {
        ldh16(qkvx + rowbase, q);
        float ss = 0.0f;
        #pragma unroll
        for (int i = 0; i < 4; i++)
            ss += q[i].x * q[i].x + q[i].y * q[i].y + q[i].z * q[i].z + q[i].w * q[i].w;
        float inv = 1.0f / fmaxf(sqrtf(ss), 1e-12f);
        #pragma unroll
        for (int i = 0; i < 4; i++) { q[i].x *= inv; q[i].y *= inv; q[i].z *= inv; q[i].w *= inv; }
    }
    {
        float4 kv[4];
        ldh16(qkvx + rowbase + 96, kv);
        float ss = 0.0f;
        #pragma unroll
        for (int i = 0; i < 4; i++)
            ss += kv[i].x * kv[i].x + kv[i].y * kv[i].y + kv[i].z * kv[i].z + kv[i].w * kv[i].w;
        float inv = 1.0f / fmaxf(sqrtf(ss), 1e-12f);
        #pragma unroll
        for (int i = 0; i < 4; i++)
            ks[n][i] = make_float4(kv[i].x * inv, kv[i].y * inv, kv[i].z * inv, kv[i].w * inv);
        float4 vv[4];
        ldh16(qkvx + rowbase + 192, vv);
        #pragma unroll
        for (int i = 0; i < 4; i++) vs[n][i] = vv[i];
    }
    {
        float4 kv[4];
        ldh16(qkvr + rowbase + 96, kv);
        float ss = 0.0f;
        #pragma unroll
        for (int i = 0; i < 4; i++)
            ss += kv[i].x * kv[i].x + kv[i].y * kv[i].y + kv[i].z * kv[i].z + kv[i].w * kv[i].w;
        float inv = 1.0f / fmaxf(sqrtf(ss), 1e-12f);
        #pragma unroll
        for (int i = 0; i < 4; i++)
            krs[n][i] = make_float4(kv[i].x * inv, kv[i].y * inv, kv[i].z * inv, kv[i].w * inv);
        float4 vv[4];
        ldh16(qkvr + rowbase + 192, vv);
        #pragma unroll
        for (int i = 0; i < 4; i++) vrs[n][i] = vv[i];
    }
    for (int idx = n; idx < 225; idx += 64) rpb_s[idx] = rpbt[idx * 6 + head];

    float lsv = expf(fminf(lsp[head], 4.605170185988092f));
    float gv  = 1.0f / (1.0f + expf(-gat[head]));
    int cnt1 = regio(wh, i1) * 3 + regio(ww, j1);
    __syncthreads();

    float4 o1[4], o2[4];
    attn_pass(ks,  vs,  q, lsv, rpb_s, i1, j1, cnt1, wh, ww, o1);
    attn_pass(krs, vrs, q, lsv, rpb_s, i1, j1, cnt1, wh, ww, o2);

    float4* op = (float4*)(out + tok * 96 + head * 16);
    __half2* oh = (__half2*)(out16 + tok * 96 + head * 16);
    float og = 1.0f - gv;
    #pragma unroll
    for (int i = 0; i < 4; i++) {
        float4 v = make_float4(og * o1[i].x + gv * o2[i].x,
                               og * o1[i].y + gv * o2[i].y,
                               og * o1[i].z + gv * o2[i].z,
                               og * o1[i].w + gv * o2[i].w);
        op[i] = v;
        oh[2 * i]     = __floats2half2_rn(v.x, v.y);
        oh[2 * i + 1] = __floats2half2_rn(v.z, v.w);
    }
}

// ---------------------------------------------------------------------------
// Host orchestration
// ---------------------------------------------------------------------------
static int g_attr_done = 0;

extern "C" void kernel_launch(void* const* d_in, const int* in_sizes, int n_in,
                              void* d_out, int out_size)
{
    const float* x       = (const float*)d_in[0];
    const float* ref     = (const float*)d_in[1];
    const float* n1g     = (const float*)d_in[2];
    const float* n1b     = (const float*)d_in[3];
    const float* qkv_w   = (const float*)d_in[4];
    const float* qkv_b   = (const float*)d_in[5];
    const float* lscale  = (const float*)d_in[6];
    const float* gating  = (const float*)d_in[7];
    const float* rpbt    = (const float*)d_in[8];
    const float* trunk_w = (const float*)d_in[9];
    const float* trunk_b = (const float*)d_in[10];
    const float* proj_w  = (const float*)d_in[11];
    const float* proj_b  = (const float*)d_in[12];
    const float* n2g     = (const float*)d_in[13];
    const float* n2b     = (const float*)d_in[14];
    const float* fc1_w   = (const float*)d_in[15];
    const float* fc1_b   = (const float*)d_in[16];
    const float* convm_w = (const float*)d_in[17];
    const float* convm_b = (const float*)d_in[18];
    const float* fc2_w   = (const float*)d_in[19];
    const float* fc2_b   = (const float*)d_in[20];
    float* out = (float*)d_out;

    float *ybuf, *x2;
    __half *qkvx16, *qkvr16, *ln16, *lnr16, *y16, *t16, *h16, *h16b;
    __half *qkvw16, *projw16, *fc1w16, *fc2w16, *trunkw16, *convmw16;
    cudaGetSymbolAddress((void**)&ybuf, g_y);
    cudaGetSymbolAddress((void**)&x2,   g_x2);
    cudaGetSymbolAddress((void**)&qkvx16, g_qkvx16);
    cudaGetSymbolAddress((void**)&qkvr16, g_qkvr16);
    cudaGetSymbolAddress((void**)&ln16, g_ln16);
    cudaGetSymbolAddress((void**)&lnr16,g_lnr16);
    cudaGetSymbolAddress((void**)&y16,  g_y16);
    cudaGetSymbolAddress((void**)&t16,  g_t16);
    cudaGetSymbolAddress((void**)&h16,  g_h16);
    cudaGetSymbolAddress((void**)&h16b, g_h16b);
    cudaGetSymbolAddress((void**)&qkvw16,  g_qkvw16);
    cudaGetSymbolAddress((void**)&projw16, g_projw16);
    cudaGetSymbolAddress((void**)&fc1w16,  g_fc1w16);
    cudaGetSymbolAddress((void**)&fc2w16,  g_fc2w16);
    cudaGetSymbolAddress((void**)&trunkw16,g_trunkw16);
    cudaGetSymbolAddress((void**)&convmw16,g_convmw16);

    const int CONV_SMEM    = (9 * 48 * 20 + 324 * 20) * 4;   // 60480
    const int GEMM_SMEM96  = (128 * 52 + 96 * 52) * 4;       // 46592
    const int GEMM_SMEM192 = (128 * 100 + 96 * 100) * 4;     // 89600

    if (!g_attr_done) {
        cudaFuncSetAttribute(conv_h<96, 96, 1, 0, 0, 1>,   cudaFuncAttributeMaxDynamicSharedMemorySize, CONV_SMEM);
        cudaFuncSetAttribute(conv_h<96, 96, 0, 1, 1, 1>,   cudaFuncAttributeMaxDynamicSharedMemorySize, CONV_SMEM);
        cudaFuncSetAttribute(conv_h<192, 192, 2, 0, 0, 1>, cudaFuncAttributeMaxDynamicSharedMemorySize, CONV_SMEM);
        cudaFuncSetAttribute(gemm_h<96, 0, 3>,  cudaFuncAttributeMaxDynamicSharedMemorySize, GEMM_SMEM96);
        cudaFuncSetAttribute(gemm_h<96, 1, 3>,  cudaFuncAttributeMaxDynamicSharedMemorySize, GEMM_SMEM96);
        cudaFuncSetAttribute(gemm_h<96, 0, 1>,  cudaFuncAttributeMaxDynamicSharedMemorySize, GEMM_SMEM96);
        cudaFuncSetAttribute(gemm_h<192, 0, 2>, cudaFuncAttributeMaxDynamicSharedMemorySize, GEMM_SMEM192);
        g_attr_done = 1;
    }

    // 1-2: conversions (trunk weights before conv1; qkv weights before gemm)
    tohalfT_k<<<(36 * 96 * 96 + 255) / 256, 256>>>(trunk_w, trunkw16, 96, 96, 36);
    tohalf_k<<<(288 * 96 + 255) / 256, 256>>>(qkv_w, qkvw16, 288 * 96);

    // 3: fused LN1 (x and ref), roll(-4,-4)
    ln2_kernel<<<2 * (TOK / 8), 256>>>(x, ref, n1g, n1b, ln16, lnr16);

    // 4: fused qkv (groups 0-2: x; 3-4: ref k,v)
    gemm_h<96, 0, 3><<<dim3(TOK / 128, 5), 256, GEMM_SMEM96>>>(
        ln16, lnr16, qkvw16, qkv_b, nullptr, nullptr, qkvx16, qkvr16, 288, 3);

    // 5: attention
    attn_kernel<<<Bb * 1024 * HEADS, 64>>>(qkvx16, qkvr16, lscale, gating, rpbt, ybuf, y16);

    // 6-9: trunk convs (48 couts per CTA => 3 CTAs/SM)
    conv_h<96, 96, 1, 0, 0, 1><<<dim3(16, 16, Bb * 2), 256, CONV_SMEM>>>(y16, trunkw16,              trunk_b,       nullptr, nullptr, t16);
    conv_h<96, 96, 0, 1, 1, 1><<<dim3(16, 16, Bb * 2), 256, CONV_SMEM>>>(t16, trunkw16 + 1 * 82944, trunk_b + 96,  ybuf, ybuf, y16);
    conv_h<96, 96, 1, 0, 0, 1><<<dim3(16, 16, Bb * 2), 256, CONV_SMEM>>>(y16, trunkw16 + 2 * 82944, trunk_b + 192, nullptr, nullptr, t16);
    conv_h<96, 96, 0, 1, 1, 1><<<dim3(16, 16, Bb * 2), 256, CONV_SMEM>>>(t16, trunkw16 + 3 * 82944, trunk_b + 288, ybuf, ybuf, y16);

    // 10-11: proj + roll back + residual
    tohalf_k<<<(96 * 96 + 255) / 256, 256>>>(proj_w, projw16, 96 * 96);
    gemm_h<96, 0, 1><<<dim3(TOK / 128, 1), 256, GEMM_SMEM96>>>(
        y16, y16, projw16, proj_b, x, x2, nullptr, nullptr, 96, 99);

    // 12-14: LN2 + fc1 (gelu)
    ln_kernel<<<TOK / 8, 256>>>(x2, n2g, n2b, t16, 0);
    tohalf_k<<<(192 * 96 + 255) / 256, 256>>>(fc1_w, fc1w16, 192 * 96);
    gemm_h<96, 1, 3><<<dim3(TOK / 128, 2), 256, GEMM_SMEM96>>>(
        t16, t16, fc1w16, fc1_b, nullptr, nullptr, h16, h16, 192, 99);

    // 15-16: convm (4 cout quarters per batch)
    tohalfT_k<<<(9 * 192 * 192 + 255) / 256, 256>>>(convm_w, convmw16, 192, 192, 9);
    conv_h<192, 192, 2, 0, 0, 1><<<dim3(16, 16, Bb * 4), 256, CONV_SMEM>>>(h16, convmw16, convm_b, nullptr, nullptr, h16b);

    // 17-18: fc2 + residual -> out
    tohalf_k<<<(96 * 192 + 255) / 256, 256>>>(fc2_w, fc2w16, 96 * 192);
    gemm_h<192, 0, 2><<<dim3(TOK / 128, 1), 256, GEMM_SMEM192>>>(
        h16b, h16b, fc2w16, fc2_b, x2, out, nullptr, nullptr, 96, 99);
}

// round 15
// speedup vs baseline: 2.0720x; 2.0720x over previous
#include <cuda_runtime.h>
#include <cuda_fp16.h>
#include <math.h>
#include <stdint.h>

// ---------------------------------------------------------------------------
// Problem constants
// ---------------------------------------------------------------------------
constexpr int Bb   = 2;
constexpr int Cc   = 96;
constexpr int HEADS= 6;
constexpr int TOK  = Bb * 256 * 256;          // 131072 tokens

// ---------------------------------------------------------------------------
// Static device scratch
// ---------------------------------------------------------------------------
__device__ float g_y   [TOK * Cc];            // fp32 residual carrier
__device__ float g_x2  [TOK * Cc];

__device__ __half g_qkvx16[TOK * 288];
__device__ __half g_qkvr16[TOK * 288];
__device__ __half g_ln16 [TOK * 96];
__device__ __half g_lnr16[TOK * 96];
__device__ __half g_y16  [TOK * 96];
__device__ __half g_t16  [TOK * 96];
__device__ __half g_h16  [TOK * 192];
__device__ __half g_h16b [TOK * 192];

__device__ __half g_qkvw16[288 * 96];
__device__ __half g_projw16[96 * 96];
__device__ __half g_fc1w16[192 * 96];
__device__ __half g_fc2w16[96 * 192];
__device__ __half g_trunkw16[36 * 96 * 96];   // [layer*9+tap][co][ci]
__device__ __half g_convmw16[9 * 192 * 192];  // [tap][co][ci]

#define DEV __device__ __forceinline__

DEV float gelu_f(float v) { return 0.5f * v * (1.0f + erff(v * 0.70710678118654752f)); }

// D += A(16x16, f16, row) * B(16x8, f16, col), fp32 accum
DEV void mma_f16(float* c, const unsigned* a, const unsigned* b) {
    asm("mma.sync.aligned.m16n8k16.row.col.f32.f16.f16.f32 "
        "{%0,%1,%2,%3}, {%4,%5,%6,%7}, {%8,%9}, {%0,%1,%2,%3};"
        : "+f"(c[0]), "+f"(c[1]), "+f"(c[2]), "+f"(c[3])
        : "r"(a[0]), "r"(a[1]), "r"(a[2]), "r"(a[3]), "r"(b[0]), "r"(b[1]));
}

DEV unsigned sa(const void* p) { return (unsigned)__cvta_generic_to_shared(p); }

DEV void cpa16(unsigned dst, const void* src) {
    asm volatile("cp.async.cg.shared.global [%0], [%1], 16;"
                 :: "r"(dst), "l"(__cvta_generic_to_global(src)));
}
DEV void cpa_commit_wait() {
    asm volatile("cp.async.commit_group;");
    asm volatile("cp.async.wait_group 0;" ::: "memory");
}

// 16 consecutive halves -> 4 float4
DEV void ldh16(const __half* p, float4* o) {
    uint4 u = *(const uint4*)p;
    uint4 v = *(const uint4*)(p + 8);
    const __half2* h0 = (const __half2*)&u;
    const __half2* h1 = (const __half2*)&v;
    float2 a0 = __half22float2(h0[0]), a1 = __half22float2(h0[1]);
    float2 a2 = __half22float2(h0[2]), a3 = __half22float2(h0[3]);
    float2 b0 = __half22float2(h1[0]), b1 = __half22float2(h1[1]);
    float2 b2 = __half22float2(h1[2]), b3 = __half22float2(h1[3]);
    o[0] = make_float4(a0.x, a0.y, a1.x, a1.y);
    o[1] = make_float4(a2.x, a2.y, a3.x, a3.y);
    o[2] = make_float4(b0.x, b0.y, b1.x, b1.y);
    o[3] = make_float4(b2.x, b2.y, b3.x, b3.y);
}

// ---------------------------------------------------------------------------
// Weight conversion kernels
// ---------------------------------------------------------------------------
__global__ void tohalf_k(const float* __restrict__ src, __half* __restrict__ dst, int n)
{
    int i = blockIdx.x * 256 + threadIdx.x;
    if (i < n) dst[i] = __float2half_rn(src[i]);
}

// fp32 [tap][ci][co] -> fp16 [tap][co][ci]
__global__ void tohalfT_k(const float* __restrict__ src, __half* __restrict__ dst,
                          int CI, int CO, int ntap)
{
    int i = blockIdx.x * 256 + threadIdx.x;
    if (i >= ntap * CI * CO) return;
    int ci = i % CI, co = (i / CI) % CO, tap = i / (CI * CO);
    dst[i] = __float2half_rn(src[((size_t)tap * CI + ci) * CO + co]);
}

// ---------------------------------------------------------------------------
// LayerNorm: single and fused-dual variants; fp16 output
// ---------------------------------------------------------------------------
DEV void ln_body(const float* src, const float* g, const float* bt, __half* dst, int lane)
{
    float v0 = src[lane], v1 = src[lane + 32], v2 = src[lane + 64];
    float s = v0 + v1 + v2;
    #pragma unroll
    for (int o = 16; o > 0; o >>= 1) s += __shfl_xor_sync(0xffffffffu, s, o);
    float mu = s * (1.0f / 96.0f);
    float d0 = v0 - mu, d1 = v1 - mu, d2 = v2 - mu;
    float sq = d0 * d0 + d1 * d1 + d2 * d2;
    #pragma unroll
    for (int o = 16; o > 0; o >>= 1) sq += __shfl_xor_sync(0xffffffffu, sq, o);
    float inv = rsqrtf(sq * (1.0f / 96.0f) + 1e-5f);
    dst[lane]      = __float2half_rn(d0 * inv * g[lane]      + bt[lane]);
    dst[lane + 32] = __float2half_rn(d1 * inv * g[lane + 32] + bt[lane + 32]);
    dst[lane + 64] = __float2half_rn(d2 * inv * g[lane + 64] + bt[lane + 64]);
}

__global__ void ln_kernel(const float* __restrict__ in, const float* __restrict__ g,
                          const float* __restrict__ bt, __half* __restrict__ out, int shift)
{
    int gid  = blockIdx.x * blockDim.x + threadIdx.x;
    int tok  = gid >> 5;
    int lane = gid & 31;
    if (tok >= TOK) return;
    int b = tok >> 16, rr = tok & 65535, h = rr >> 8, w = rr & 255;
    const float* src = in + (size_t)((b << 16) | (((h + shift) & 255) << 8) | ((w + shift) & 255)) * 96;
    ln_body(src, g, bt, out + (size_t)tok * 96, lane);
}

__global__ void ln2_kernel(const float* __restrict__ in0, const float* __restrict__ in1,
                           const float* __restrict__ g, const float* __restrict__ bt,
                           __half* __restrict__ out0, __half* __restrict__ out1)
{
    int half = gridDim.x >> 1;
    int bid = blockIdx.x;
    const float* in = (bid < half) ? in0 : in1;
    __half* out = (bid < half) ? out0 : out1;
    int bb = (bid < half) ? bid : bid - half;
    int gid = bb * blockDim.x + threadIdx.x;
    int tok = gid >> 5, lane = gid & 31;
    if (tok >= TOK) return;
    int b = tok >> 16, rr = tok & 65535, h = rr >> 8, w = rr & 255;
    const float* src = in + (size_t)((b << 16) | (((h + 4) & 255) << 8) | ((w + 4) & 255)) * 96;
    ln_body(src, g, bt, out + (size_t)tok * 96, lane);
}

// ---------------------------------------------------------------------------
// Tensor-core GEMM (fp16 m16n8k16), cp.async staging from fp16 mirrors.
// Block: 128 rows x 96 cols, 8 warps (4 Mquad x 2 Nhalf); warp 2x6 frags.
// Fused input select: blockIdx.y < split -> (Ax, o16x, n0 = y*96)
//                     else              -> (Ar, o16r, n0 = (y-split+1)*96)
// MODE 1 proj roll+res fp32, 2 res fp32, 3 fp16 plain. ACT 0 none, 1 gelu.
// ---------------------------------------------------------------------------
template<int K, int ACT, int MODE>
__global__ void __launch_bounds__(256) gemm_h(
        const __half* __restrict__ Ax, const __half* __restrict__ Ar,
        const __half* __restrict__ W, const float* __restrict__ bias,
        const float* __restrict__ res, float* __restrict__ out32,
        __half* __restrict__ o16x, __half* __restrict__ o16r,
        int outN, int split)
{
    constexpr int KP = K / 2;
    constexpr int AP = KP + 4;                  // 52 or 100
    constexpr int CH = K / 8;
    extern __shared__ unsigned smem_u[];
    unsigned* As = smem_u;
    unsigned* Ws = smem_u + 128 * AP;

    int y = blockIdx.y;
    const __half* A; __half* o16; int n0;
    if (y < split) { A = Ax; o16 = o16x; n0 = y * 96; }
    else           { A = Ar; o16 = o16r; n0 = (y - split + 1) * 96; }

    int m0 = blockIdx.x * 128;
    int t  = threadIdx.x;
    int warp = t >> 5, lane = t & 31;
    int wm = warp >> 1, wn = warp & 1;
    int g = lane >> 2, tg = lane & 3;

    unsigned as_base = sa(As), ws_base = sa(Ws);
    #pragma unroll
    for (int i = 0; i < 128 * CH / 256; i++) {
        int idx = t + i * 256;
        int m = idx / CH, c = idx % CH;
        cpa16(as_base + (unsigned)(m * AP + c * 4) * 4, A + (size_t)(m0 + m) * K + c * 8);
    }
    for (int idx = t; idx < 96 * CH; idx += 256) {
        int c = idx / CH, ck = idx % CH;
        cpa16(ws_base + (unsigned)(c * AP + ck * 4) * 4, W + (size_t)(n0 + c) * K + ck * 8);
    }
    cpa_commit_wait();
    __syncthreads();

    float acc[2][6][4];
    #pragma unroll
    for (int i = 0; i < 2; i++)
        #pragma unroll
        for (int j = 0; j < 6; j++)
            #pragma unroll
            for (int q = 0; q < 4; q++) acc[i][j][q] = 0.0f;

    #pragma unroll
    for (int s = 0; s < K / 16; s++) {
        int kb = s * 8;
        unsigned a[2][4];
        #pragma unroll
        for (int i = 0; i < 2; i++) {
            int mb = (wm * 2 + i) * 16;
            a[i][0] = As[(mb + g)     * AP + kb + tg];
            a[i][1] = As[(mb + g + 8) * AP + kb + tg];
            a[i][2] = As[(mb + g)     * AP + kb + tg + 4];
            a[i][3] = As[(mb + g + 8) * AP + kb + tg + 4];
        }
        unsigned b[6][2];
        #pragma unroll
        for (int j = 0; j < 6; j++) {
            int col = wn * 48 + j * 8 + g;
            b[j][0] = Ws[col * AP + kb + tg];
            b[j][1] = Ws[col * AP + kb + tg + 4];
        }
        #pragma unroll
        for (int i = 0; i < 2; i++)
            #pragma unroll
            for (int j = 0; j < 6; j++) mma_f16(acc[i][j], a[i], b[j]);
    }

    #pragma unroll
    for (int i = 0; i < 2; i++) {
        int rb = m0 + (wm * 2 + i) * 16;
        #pragma unroll
        for (int j = 0; j < 6; j++) {
            int c = wn * 48 + j * 8 + tg * 2;
            #pragma unroll
            for (int half = 0; half < 2; half++) {
                int row = rb + g + half * 8;
                float v0 = acc[i][j][half * 2]     + bias[n0 + c];
                float v1 = acc[i][j][half * 2 + 1] + bias[n0 + c + 1];
                if (ACT == 1) { v0 = gelu_f(v0); v1 = gelu_f(v1); }
                if (MODE == 1) {
                    int bb = row >> 16, rr = row & 65535, hy = rr >> 8, wx = rr & 255;
                    int tr = (bb << 16) | (((hy + 4) & 255) << 8) | ((wx + 4) & 255);
                    out32[(size_t)tr * 96 + c]     = res[(size_t)tr * 96 + c]     + v0;
                    out32[(size_t)tr * 96 + c + 1] = res[(size_t)tr * 96 + c + 1] + v1;
                } else if (MODE == 2) {
                    out32[(size_t)row * 96 + c]     = res[(size_t)row * 96 + c]     + v0;
                    out32[(size_t)row * 96 + c + 1] = res[(size_t)row * 96 + c + 1] + v1;
                } else {
                    *(__half2*)&o16[(size_t)row * outN + n0 + c] =
                        __floats2half2_rn(v0, v1);
                }
            }
        }
    }
}

// ---------------------------------------------------------------------------
// Tensor-core 3x3 SAME conv (implicit GEMM, fp16 m16n8k16), cp.async staging.
// Block: 16x16 pixel tile x 96 cout, 256 threads (8 warps: 4 Mquad x 2 Nhalf).
// Halo 18x18 = 324 pos, smem [324][20]; weights [9*96][20] per 32-ci chunk.
// Single buffer, 95 KB => 2 CTAs/SM (cross-CTA latency hiding).
// grid = (16, 16, b*(COUT/96)+cohalf). ACT 0/1/2 = none/relu/gelu.
// ---------------------------------------------------------------------------
template<int CIN, int COUT, int ACT, int RES, int O32, int O16>
__global__ void __launch_bounds__(256) conv_h(
        const __half* __restrict__ in16, const __half* __restrict__ w16t,
        const float* __restrict__ bias, const float* __restrict__ res,
        float* __restrict__ out32, __half* __restrict__ out16)
{
    constexpr int PIT = 20;           // kpair pitch (u32), %32 = 20
    constexpr int NH = COUT / 96;
    extern __shared__ unsigned smem_u[];
    unsigned* ws_u  = smem_u;                       // [9*96][PIT]
    unsigned* ins_u = smem_u + 9 * 96 * PIT;        // [324][PIT]

    int x0 = blockIdx.x * 16, y0 = blockIdx.y * 16;
    int zb = blockIdx.z;
    int cohalf = (NH == 1) ? 0 : (zb & 1);
    int b      = (NH == 1) ? zb : (zb >> 1);
    int t  = threadIdx.x;
    int warp = t >> 5, lane = t & 31;
    int wm = warp >> 1, wn = warp & 1;
    int g = lane >> 2, tg = lane & 3;

    unsigned ins_base = sa(ins_u), ws_base = sa(ws_u);

    float acc[4][6][4];
    #pragma unroll
    for (int i = 0; i < 4; i++)
        #pragma unroll
        for (int j = 0; j < 6; j++)
            #pragma unroll
            for (int q = 0; q < 4; q++) acc[i][j][q] = 0.0f;

    for (int ci0 = 0; ci0 < CIN; ci0 += 32) {
        // halo 18x18, 32 ci = 4 x 16B per pixel
        for (int idx = t; idx < 324 * 4; idx += 256) {
            int ck = idx & 3, pos = idx >> 2;
            int hp = pos / 18, wp = pos % 18;
            int gy = y0 + hp - 1, gx = x0 + wp - 1;
            unsigned dst = ins_base + (unsigned)(pos * PIT + ck * 4) * 4;
            if ((unsigned)gy < 256u && (unsigned)gx < 256u) {
                cpa16(dst, in16 + (size_t)((b << 16) | (gy << 8) | gx) * CIN + ci0 + ck * 8);
            } else {
                *(uint4*)&ins_u[pos * PIT + ck * 4] = make_uint4(0, 0, 0, 0);
            }
        }
        // weights: 9 taps x 96 co, 32 ci = 4 x 16B per row
        for (int idx = t; idx < 9 * 96 * 4; idx += 256) {
            int ck = idx & 3, row = idx >> 2;       // row = tap*96 + co
            int tap = row / 96, co = row % 96;
            cpa16(ws_base + (unsigned)(row * PIT + ck * 4) * 4,
                  w16t + ((size_t)tap * COUT + cohalf * 96 + co) * CIN + ci0 + ck * 8);
        }
        cpa_commit_wait();
        __syncthreads();

        #pragma unroll
        for (int dy = 0; dy < 3; dy++) {
            #pragma unroll
            for (int dx = 0; dx < 3; dx++) {
                const unsigned* wt = ws_u + (dy * 3 + dx) * 96 * PIT;
                #pragma unroll
                for (int s = 0; s < 2; s++) {
                    int cb = s * 8;
                    unsigned a[4][4];
                    #pragma unroll
                    for (int i = 0; i < 4; i++) {
                        int base = (wm * 4 + i + dy) * 18 + dx;
                        a[i][0] = ins_u[(base + g)     * PIT + cb + tg];
                        a[i][1] = ins_u[(base + g + 8) * PIT + cb + tg];
                        a[i][2] = ins_u[(base + g)     * PIT + cb + tg + 4];
                        a[i][3] = ins_u[(base + g + 8) * PIT + cb + tg + 4];
                    }
                    unsigned bfr[6][2];
                    #pragma unroll
                    for (int j = 0; j < 6; j++) {
                        int col = wn * 48 + j * 8 + g;
                        bfr[j][0] = wt[col * PIT + cb + tg];
                        bfr[j][1] = wt[col * PIT + cb + tg + 4];
                    }
                    #pragma unroll
                    for (int i = 0; i < 4; i++)
                        #pragma unroll
                        for (int j = 0; j < 6; j++) mma_f16(acc[i][j], a[i], bfr[j]);
                }
            }
        }
        __syncthreads();
    }

    #pragma unroll
    for (int i = 0; i < 4; i++) {
        int y = y0 + wm * 4 + i;
        #pragma unroll
        for (int j = 0; j < 6; j++) {
            int co = cohalf * 96 + wn * 48 + j * 8 + tg * 2;
            float b0 = bias[co], b1 = bias[co + 1];
            #pragma unroll
            for (int half = 0; half < 2; half++) {
                int x = x0 + g + half * 8;
                size_t base = (size_t)((b << 16) | (y << 8) | x) * COUT + co;
                float v0 = acc[i][j][half * 2]     + b0;
                float v1 = acc[i][j][half * 2 + 1] + b1;
                if (ACT == 1) { v0 = fmaxf(v0, 0.0f); v1 = fmaxf(v1, 0.0f); }
                if (ACT == 2) { v0 = gelu_f(v0); v1 = gelu_f(v1); }
                if (RES) { v0 += res[base]; v1 += res[base + 1]; }
                if (O32) { out32[base] = v0; out32[base + 1] = v1; }
                if (O16) *(__half2*)&out16[base] = __floats2half2_rn(v0, v1);
            }
        }
    }
}

// ---------------------------------------------------------------------------
// Windowed dual attention. One block per (window, head-PAIR). 128 threads:
// thread = (head_local = t>>6, row n = t&63). Math identical to 64-thread ver.
// ---------------------------------------------------------------------------
DEV int regio(int wblk, int i) { return (wblk < 31) ? 0 : ((i < 4) ? 1 : 2); }

DEV void attn_pass(const float4 (*K4)[4], const float4 (*V4)[4], const float4 q[4],
                   float lsv, const float* rpb_s, int i1, int j1, int cnt1,
                   int wh, int ww, float4 o[4])
{
    float s[64];
    #pragma unroll
    for (int m = 0; m < 64; m++) {
        const float4* kr = K4[m];
        float d;
        d  = q[0].x * kr[0].x + q[0].y * kr[0].y + q[0].z * kr[0].z + q[0].w * kr[0].w;
        d += q[1].x * kr[1].x + q[1].y * kr[1].y + q[1].z * kr[1].z + q[1].w * kr[1].w;
        d += q[2].x * kr[2].x + q[2].y * kr[2].y + q[2].z * kr[2].z + q[2].w * kr[2].w;
        d += q[3].x * kr[3].x + q[3].y * kr[3].y + q[3].z * kr[3].z + q[3].w * kr[3].w;
        int i2 = m >> 3, j2 = m & 7;
        float rb = rpb_s[(i1 - i2 + 7) * 15 + (j1 - j2 + 7)];
        int cnt2 = regio(wh, i2) * 3 + regio(ww, j2);
        s[m] = d * lsv + rb + ((cnt1 != cnt2) ? -100.0f : 0.0f);
    }
    float mx = s[0];
    #pragma unroll
    for (int m = 1; m < 64; m++) mx = fmaxf(mx, s[m]);
    float sum = 0.0f;
    float4 a0 = make_float4(0, 0, 0, 0), a1 = a0, a2 = a0, a3 = a0;
    #pragma unroll
    for (int m = 0; m < 64; m++) {
        float p = expf(s[m] - mx);
        sum += p;
        const float4* vr = V4[m];
        a0.x += p * vr[0].x; a0.y += p * vr[0].y; a0.z += p * vr[0].z; a0.w += p * vr[0].w;
        a1.x += p * vr[1].x; a1.y += p * vr[1].y; a1.z += p * vr[1].z; a1.w += p * vr[1].w;
        a2.x += p * vr[2].x; a2.y += p * vr[2].y; a2.z += p * vr[2].z; a2.w += p * vr[2].w;
        a3.x += p * vr[3].x; a3.y += p * vr[3].y; a3.z += p * vr[3].z; a3.w += p * vr[3].w;
    }
    float inv = 1.0f / sum;
    o[0] = make_float4(a0.x * inv, a0.y * inv, a0.z * inv, a0.w * inv);
    o[1] = make_float4(a1.x * inv, a1.y * inv, a1.z * inv, a1.w * inv);
    o[2] = make_float4(a2.x * inv, a2.y * inv, a2.z * inv, a2.w * inv);
    o[3] = make_float4(a3.x * inv, a3.y * inv, a3.z * inv, a3.w * inv);
}

__global__ void __launch_bounds__(128) attn_kernel(
        const __half* __restrict__ qkvx, const __half* __restrict__ qkvr,
        const float* __restrict__ lsp, const float* __restrict__ gat,
        const float* __restrict__ rpbt, float* __restrict__ out,
        __half* __restrict__ out16)
{
    __shared__ float4 ks[2][64][4], vs[2][64][4], krs[2][64][4], vrs[2][64][4];
    __shared__ float rpb_s[2][225];
    int blk  = blockIdx.x;
    int hp   = blk % (HEADS / 2);          // head pair 0..2
    int widx = blk / (HEADS / 2);
    int b  = widx >> 10;
    int nw = widx & 1023;
    int wh = nw >> 5, ww = nw & 31;
    int t  = threadIdx.x;
    int hl = t >> 6;                       // head within pair
    int n  = t & 63;                       // row within window
    int head = hp * 2 + hl;
    int i1 = n >> 3, j1 = n & 7;

    size_t tok = (size_t)((b << 16) | ((wh * 8 + i1) << 8) | (ww * 8 + j1));
    size_t rowbase = tok * 288 + head * 16;

    float4 q[4];
    {
        ldh16(qkvx + rowbase, q);
        float ss = 0.0f;
        #pragma unroll
        for (int i = 0; i < 4; i++)
            ss += q[i].x * q[i].x + q[i].y * q[i].y + q[i].z * q[i].z + q[i].w * q[i].w;
        float inv = 1.0f / fmaxf(sqrtf(ss), 1e-12f);
        #pragma unroll
        for (int i = 0; i < 4; i++) { q[i].x *= inv; q[i].y *= inv; q[i].z *= inv; q[i].w *= inv; }
    }
    {
        float4 kv[4];
        ldh16(qkvx + rowbase + 96, kv);
        float ss = 0.0f;
        #pragma unroll
        for (int i = 0; i < 4; i++)
            ss += kv[i].x * kv[i].x + kv[i].y * kv[i].y + kv[i].z * kv[i].z + kv[i].w * kv[i].w;
        float inv = 1.0f / fmaxf(sqrtf(ss), 1e-12f);
        #pragma unroll
        for (int i = 0; i < 4; i++)
            ks[hl][n][i] = make_float4(kv[i].x * inv, kv[i].y * inv, kv[i].z * inv, kv[i].w * inv);
        float4 vv[4];
        ldh16(qkvx + rowbase + 192, vv);
        #pragma unroll
        for (int i = 0; i < 4; i++) vs[hl][n][i] = vv[i];
    }
    {
        float4 kv[4];
        ldh16(qkvr + rowbase + 96, kv);
        float ss = 0.0f;
        #pragma unroll
        for (int i = 0; i < 4; i++)
            ss += kv[i].x * kv[i].x + kv[i].y * kv[i].y + kv[i].z * kv[i].z + kv[i].w * kv[i].w;
        float inv = 1.0f / fmaxf(sqrtf(ss), 1e-12f);
        #pragma unroll
        for (int i = 0; i < 4; i++)
            krs[hl][n][i] = make_float4(kv[i].x * inv, kv[i].y * inv, kv[i].z * inv, kv[i].w * inv);
        float4 vv[4];
        ldh16(qkvr + rowbase + 192, vv);
        #pragma unroll
        for (int i = 0; i < 4; i++) vrs[hl][n][i] = vv[i];
    }
    for (int idx = n; idx < 225; idx += 64) rpb_s[hl][idx] = rpbt[idx * 6 + head];

    float lsv = expf(fminf(lsp[head], 4.605170185988092f));
    float gv  = 1.0f / (1.0f + expf(-gat[head]));
    int cnt1 = regio(wh, i1) * 3 + regio(ww, j1);
    __syncthreads();

    float4 o1[4], o2[4];
    attn_pass(ks[hl],  vs[hl],  q, lsv, rpb_s[hl], i1, j1, cnt1, wh, ww, o1);
    attn_pass(krs[hl], vrs[hl], q, lsv, rpb_s[hl], i1, j1, cnt1, wh, ww, o2);

    float4* op = (float4*)(out + tok * 96 + head * 16);
    __half2* oh = (__half2*)(out16 + tok * 96 + head * 16);
    float og = 1.0f - gv;
    #pragma unroll
    for (int i = 0; i < 4; i++) {
        float4 v = make_float4(og * o1[i].x + gv * o2[i].x,
                               og * o1[i].y + gv * o2[i].y,
                               og * o1[i].z + gv * o2[i].z,
                               og * o1[i].w + gv * o2[i].w);
        op[i] = v;
        oh[2 * i]     = __floats2half2_rn(v.x, v.y);
        oh[2 * i + 1] = __floats2half2_rn(v.z, v.w);
    }
}

// ---------------------------------------------------------------------------
// Host orchestration
// ---------------------------------------------------------------------------
static int g_attr_done = 0;

extern "C" void kernel_launch(void* const* d_in, const int* in_sizes, int n_in,
                              void* d_out, int out_size)
{
    const float* x       = (const float*)d_in[0];
    const float* ref     = (const float*)d_in[1];
    const float* n1g     = (const float*)d_in[2];
    const float* n1b     = (const float*)d_in[3];
    const float* qkv_w   = (const float*)d_in[4];
    const float* qkv_b   = (const float*)d_in[5];
    const float* lscale  = (const float*)d_in[6];
    const float* gating  = (const float*)d_in[7];
    const float* rpbt    = (const float*)d_in[8];
    const float* trunk_w = (const float*)d_in[9];
    const float* trunk_b = (const float*)d_in[10];
    const float* proj_w  = (const float*)d_in[11];
    const float* proj_b  = (const float*)d_in[12];
    const float* n2g     = (const float*)d_in[13];
    const float* n2b     = (const float*)d_in[14];
    const float* fc1_w   = (const float*)d_in[15];
    const float* fc1_b   = (const float*)d_in[16];
    const float* convm_w = (const float*)d_in[17];
    const float* convm_b = (const float*)d_in[18];
    const float* fc2_w   = (const float*)d_in[19];
    const float* fc2_b   = (const float*)d_in[20];
    float* out = (float*)d_out;

    float *ybuf, *x2;
    __half *qkvx16, *qkvr16, *ln16, *lnr16, *y16, *t16, *h16, *h16b;
    __half *qkvw16, *projw16, *fc1w16, *fc2w16, *trunkw16, *convmw16;
    cudaGetSymbolAddress((void**)&ybuf, g_y);
    cudaGetSymbolAddress((void**)&x2,   g_x2);
    cudaGetSymbolAddress((void**)&qkvx16, g_qkvx16);
    cudaGetSymbolAddress((void**)&qkvr16, g_qkvr16);
    cudaGetSymbolAddress((void**)&ln16, g_ln16);
    cudaGetSymbolAddress((void**)&lnr16,g_lnr16);
    cudaGetSymbolAddress((void**)&y16,  g_y16);
    cudaGetSymbolAddress((void**)&t16,  g_t16);
    cudaGetSymbolAddress((void**)&h16,  g_h16);
    cudaGetSymbolAddress((void**)&h16b, g_h16b);
    cudaGetSymbolAddress((void**)&qkvw16,  g_qkvw16);
    cudaGetSymbolAddress((void**)&projw16, g_projw16);
    cudaGetSymbolAddress((void**)&fc1w16,  g_fc1w16);
    cudaGetSymbolAddress((void**)&fc2w16,  g_fc2w16);
    cudaGetSymbolAddress((void**)&trunkw16,g_trunkw16);
    cudaGetSymbolAddress((void**)&convmw16,g_convmw16);

    const int CONV_SMEM    = (9 * 96 * 20 + 324 * 20) * 4;   // 95040
    const int GEMM_SMEM96  = (128 * 52 + 96 * 52) * 4;       // 46592
    const int GEMM_SMEM192 = (128 * 100 + 96 * 100) * 4;     // 89600

    if (!g_attr_done) {
        cudaFuncSetAttribute(conv_h<96, 96, 1, 0, 0, 1>,   cudaFuncAttributeMaxDynamicSharedMemorySize, CONV_SMEM);
        cudaFuncSetAttribute(conv_h<96, 96, 0, 1, 1, 1>,   cudaFuncAttributeMaxDynamicSharedMemorySize, CONV_SMEM);
        cudaFuncSetAttribute(conv_h<192, 192, 2, 0, 0, 1>, cudaFuncAttributeMaxDynamicSharedMemorySize, CONV_SMEM);
        cudaFuncSetAttribute(gemm_h<96, 0, 3>,  cudaFuncAttributeMaxDynamicSharedMemorySize, GEMM_SMEM96);
        cudaFuncSetAttribute(gemm_h<96, 1, 3>,  cudaFuncAttributeMaxDynamicSharedMemorySize, GEMM_SMEM96);
        cudaFuncSetAttribute(gemm_h<96, 0, 1>,  cudaFuncAttributeMaxDynamicSharedMemorySize, GEMM_SMEM96);
        cudaFuncSetAttribute(gemm_h<192, 0, 2>, cudaFuncAttributeMaxDynamicSharedMemorySize, GEMM_SMEM192);
        g_attr_done = 1;
    }

    // 1-2: conversions (trunk weights before conv1; qkv weights before gemm)
    tohalfT_k<<<(36 * 96 * 96 + 255) / 256, 256>>>(trunk_w, trunkw16, 96, 96, 36);
    tohalf_k<<<(288 * 96 + 255) / 256, 256>>>(qkv_w, qkvw16, 288 * 96);

    // 3: fused LN1 (x and ref), roll(-4,-4)
    ln2_kernel<<<2 * (TOK / 8), 256>>>(x, ref, n1g, n1b, ln16, lnr16);

    // 4: fused qkv (groups 0-2: x; 3-4: ref k,v)
    gemm_h<96, 0, 3><<<dim3(TOK / 128, 5), 256, GEMM_SMEM96>>>(
        ln16, lnr16, qkvw16, qkv_b, nullptr, nullptr, qkvx16, qkvr16, 288, 3);

    // 5: attention (2 heads per block)
    attn_kernel<<<Bb * 1024 * (HEADS / 2), 128>>>(qkvx16, qkvr16, lscale, gating, rpbt, ybuf, y16);

    // 6-9: trunk convs
    conv_h<96, 96, 1, 0, 0, 1><<<dim3(16, 16, Bb), 256, CONV_SMEM>>>(y16, trunkw16,              trunk_b,       nullptr, nullptr, t16);
    conv_h<96, 96, 0, 1, 1, 1><<<dim3(16, 16, Bb), 256, CONV_SMEM>>>(t16, trunkw16 + 1 * 82944, trunk_b + 96,  ybuf, ybuf, y16);
    conv_h<96, 96, 1, 0, 0, 1><<<dim3(16, 16, Bb), 256, CONV_SMEM>>>(y16, trunkw16 + 2 * 82944, trunk_b + 192, nullptr, nullptr, t16);
    conv_h<96, 96, 0, 1, 1, 1><<<dim3(16, 16, Bb), 256, CONV_SMEM>>>(t16, trunkw16 + 3 * 82944, trunk_b + 288, ybuf, ybuf, y16);

    // 10-11: proj + roll back + residual
    tohalf_k<<<(96 * 96 + 255) / 256, 256>>>(proj_w, projw16, 96 * 96);
    gemm_h<96, 0, 1><<<dim3(TOK / 128, 1), 256, GEMM_SMEM96>>>(
        y16, y16, projw16, proj_b, x, x2, nullptr, nullptr, 96, 99);

    // 12-14: LN2 + fc1 (gelu)
    ln_kernel<<<TOK / 8, 256>>>(x2, n2g, n2b, t16, 0);
    tohalf_k<<<(192 * 96 + 255) / 256, 256>>>(fc1_w, fc1w16, 192 * 96);
    gemm_h<96, 1, 3><<<dim3(TOK / 128, 2), 256, GEMM_SMEM96>>>(
        t16, t16, fc1w16, fc1_b, nullptr, nullptr, h16, h16, 192, 99);

    // 15-16: convm
    tohalfT_k<<<(9 * 192 * 192 + 255) / 256, 256>>>(convm_w, convmw16, 192, 192, 9);
    conv_h<192, 192, 2, 0, 0, 1><<<dim3(16, 16, Bb * 2), 256, CONV_SMEM>>>(h16, convmw16, convm_b, nullptr, nullptr, h16b);

    // 17-18: fc2 + residual -> out
    tohalf_k<<<(96 * 192 + 255) / 256, 256>>>(fc2_w, fc2w16, 96 * 192);
    gemm_h<192, 0, 2><<<dim3(TOK / 128, 1), 256, GEMM_SMEM192>>>(
        h16b, h16b, fc2w16, fc2_b, x2, out, nullptr, nullptr, 96, 99);
}

// round 16
// speedup vs baseline: 2.1331x; 1.0295x over previous
#include <cuda_runtime.h>
#include <cuda_fp16.h>
#include <math.h>
#include <stdint.h>

// ---------------------------------------------------------------------------
// Problem constants
// ---------------------------------------------------------------------------
constexpr int Bb   = 2;
constexpr int Cc   = 96;
constexpr int HEADS= 6;
constexpr int TOK  = Bb * 256 * 256;          // 131072 tokens

// ---------------------------------------------------------------------------
// Static device scratch
// ---------------------------------------------------------------------------
__device__ float g_y   [TOK * Cc];            // fp32 residual carrier
__device__ float g_x2  [TOK * Cc];

__device__ __half g_qkvx16[TOK * 288];
__device__ __half g_qkvr16[TOK * 288];
__device__ __half g_ln16 [TOK * 96];
__device__ __half g_lnr16[TOK * 96];
__device__ __half g_y16  [TOK * 96];
__device__ __half g_t16  [TOK * 96];
__device__ __half g_h16  [TOK * 192];
__device__ __half g_h16b [TOK * 192];

__device__ __half g_qkvw16[288 * 96];         // k-pair permuted
__device__ __half g_projw16[96 * 96];         // k-pair permuted
__device__ __half g_fc1w16[192 * 96];         // k-pair permuted
__device__ __half g_fc2w16[96 * 192];         // k-pair permuted
__device__ __half g_trunkw16[36 * 96 * 96];   // [layer*9+tap][co][ci], ci-permuted
__device__ __half g_convmw16[9 * 192 * 192];  // [tap][co][ci], ci-permuted

#define DEV __device__ __forceinline__

DEV float gelu_f(float v) { return 0.5f * v * (1.0f + erff(v * 0.70710678118654752f)); }

// D += A(16x16, f16, row) * B(16x8, f16, col), fp32 accum
DEV void mma_f16(float* c, const unsigned* a, const unsigned* b) {
    asm("mma.sync.aligned.m16n8k16.row.col.f32.f16.f16.f32 "
        "{%0,%1,%2,%3}, {%4,%5,%6,%7}, {%8,%9}, {%0,%1,%2,%3};"
        : "+f"(c[0]), "+f"(c[1]), "+f"(c[2]), "+f"(c[3])
        : "r"(a[0]), "r"(a[1]), "r"(a[2]), "r"(a[3]), "r"(b[0]), "r"(b[1]));
}

DEV unsigned sa(const void* p) { return (unsigned)__cvta_generic_to_shared(p); }

DEV void cpa16(unsigned dst, const void* src) {
    asm volatile("cp.async.cg.shared.global [%0], [%1], 16;"
                 :: "r"(dst), "l"(__cvta_generic_to_global(src)));
}
DEV void cpa_commit_wait() {
    asm volatile("cp.async.commit_group;");
    asm volatile("cp.async.wait_group 0;" ::: "memory");
}

// 16 consecutive halves -> 4 float4
DEV void ldh16(const __half* p, float4* o) {
    uint4 u = *(const uint4*)p;
    uint4 v = *(const uint4*)(p + 8);
    const __half2* h0 = (const __half2*)&u;
    const __half2* h1 = (const __half2*)&v;
    float2 a0 = __half22float2(h0[0]), a1 = __half22float2(h0[1]);
    float2 a2 = __half22float2(h0[2]), a3 = __half22float2(h0[3]);
    float2 b0 = __half22float2(h1[0]), b1 = __half22float2(h1[1]);
    float2 b2 = __half22float2(h1[2]), b3 = __half22float2(h1[3]);
    o[0] = make_float4(a0.x, a0.y, a1.x, a1.y);
    o[1] = make_float4(a2.x, a2.y, a3.x, a3.y);
    o[2] = make_float4(b0.x, b0.y, b1.x, b1.y);
    o[3] = make_float4(b2.x, b2.y, b3.x, b3.y);
}

// ---------------------------------------------------------------------------
// Weight conversion kernels (with k-pair permutation for LDS.64 B-frags)
// slot q for natural pair p within each 8-pair (16-elem) block: [0,4,1,5,2,6,3,7]
// => slot 2tg holds pair tg, slot 2tg+1 holds pair tg+4.
// ---------------------------------------------------------------------------
__global__ void tohalfp_k(const float* __restrict__ src, __half* __restrict__ dst,
                          int n, int K)
{
    int i = blockIdx.x * 256 + threadIdx.x;
    if (i >= n) return;
    int k = i % K, o = i / K;
    int blk = k >> 4, r = k & 15;
    int p = r >> 1, lo = r & 1;
    int q = (p & 3) * 2 + (p >> 2);
    int kd = blk * 16 + q * 2 + lo;
    dst[(size_t)o * K + kd] = __float2half_rn(src[i]);
}

// fp32 [tap][ci][co] -> fp16 [tap][co][ci] with ci-pair permutation
__global__ void tohalfTp_k(const float* __restrict__ src, __half* __restrict__ dst,
                           int CI, int CO, int ntap)
{
    int i = blockIdx.x * 256 + threadIdx.x;
    if (i >= ntap * CI * CO) return;
    int ci = i % CI, co = (i / CI) % CO, tap = i / (CI * CO);
    int blk = ci >> 4, r = ci & 15;
    int p = r >> 1, lo = r & 1;
    int q = (p & 3) * 2 + (p >> 2);
    int cid = blk * 16 + q * 2 + lo;
    dst[((size_t)tap * CO + co) * CI + cid] =
        __float2half_rn(src[((size_t)tap * CI + ci) * CO + co]);
}

// ---------------------------------------------------------------------------
// LayerNorm: single and fused-dual variants; fp16 output
// ---------------------------------------------------------------------------
DEV void ln_body(const float* src, const float* g, const float* bt, __half* dst, int lane)
{
    float v0 = src[lane], v1 = src[lane + 32], v2 = src[lane + 64];
    float s = v0 + v1 + v2;
    #pragma unroll
    for (int o = 16; o > 0; o >>= 1) s += __shfl_xor_sync(0xffffffffu, s, o);
    float mu = s * (1.0f / 96.0f);
    float d0 = v0 - mu, d1 = v1 - mu, d2 = v2 - mu;
    float sq = d0 * d0 + d1 * d1 + d2 * d2;
    #pragma unroll
    for (int o = 16; o > 0; o >>= 1) sq += __shfl_xor_sync(0xffffffffu, sq, o);
    float inv = rsqrtf(sq * (1.0f / 96.0f) + 1e-5f);
    dst[lane]      = __float2half_rn(d0 * inv * g[lane]      + bt[lane]);
    dst[lane + 32] = __float2half_rn(d1 * inv * g[lane + 32] + bt[lane + 32]);
    dst[lane + 64] = __float2half_rn(d2 * inv * g[lane + 64] + bt[lane + 64]);
}

__global__ void ln_kernel(const float* __restrict__ in, const float* __restrict__ g,
                          const float* __restrict__ bt, __half* __restrict__ out, int shift)
{
    int gid  = blockIdx.x * blockDim.x + threadIdx.x;
    int tok  = gid >> 5;
    int lane = gid & 31;
    if (tok >= TOK) return;
    int b = tok >> 16, rr = tok & 65535, h = rr >> 8, w = rr & 255;
    const float* src = in + (size_t)((b << 16) | (((h + shift) & 255) << 8) | ((w + shift) & 255)) * 96;
    ln_body(src, g, bt, out + (size_t)tok * 96, lane);
}

__global__ void ln2_kernel(const float* __restrict__ in0, const float* __restrict__ in1,
                           const float* __restrict__ g, const float* __restrict__ bt,
                           __half* __restrict__ out0, __half* __restrict__ out1)
{
    int half = gridDim.x >> 1;
    int bid = blockIdx.x;
    const float* in = (bid < half) ? in0 : in1;
    __half* out = (bid < half) ? out0 : out1;
    int bb = (bid < half) ? bid : bid - half;
    int gid = bb * blockDim.x + threadIdx.x;
    int tok = gid >> 5, lane = gid & 31;
    if (tok >= TOK) return;
    int b = tok >> 16, rr = tok & 65535, h = rr >> 8, w = rr & 255;
    const float* src = in + (size_t)((b << 16) | (((h + 4) & 255) << 8) | ((w + 4) & 255)) * 96;
    ln_body(src, g, bt, out + (size_t)tok * 96, lane);
}

// ---------------------------------------------------------------------------
// Tensor-core GEMM (fp16 m16n8k16), cp.async staging from fp16 mirrors.
// Block: 128 rows x 96 cols, 8 warps (4 Mquad x 2 Nhalf); warp 2x6 frags.
// Weights k-pair-permuted => B-frag = one LDS.64 per n-frag per k-step.
// Ws pitch WPW: 56 (K=96) / 104 (K=192): conflict-free for LDS.64.
// MODE 1 proj roll+res fp32, 2 res fp32, 3 fp16 plain. ACT 0 none, 1 gelu.
// ---------------------------------------------------------------------------
template<int K, int ACT, int MODE>
__global__ void __launch_bounds__(256) gemm_h(
        const __half* __restrict__ Ax, const __half* __restrict__ Ar,
        const __half* __restrict__ W, const float* __restrict__ bias,
        const float* __restrict__ res, float* __restrict__ out32,
        __half* __restrict__ o16x, __half* __restrict__ o16r,
        int outN, int split)
{
    constexpr int KP  = K / 2;
    constexpr int AP  = KP + 4;                 // A pitch: 52 or 100
    constexpr int WPW = (K == 96) ? 56 : 104;   // W pitch (LDS.64-conflict-free)
    constexpr int CH  = K / 8;
    extern __shared__ unsigned smem_u[];
    unsigned* As = smem_u;                      // 128*AP
    unsigned* Ws = smem_u + 128 * AP;           // 96*WPW

    int y = blockIdx.y;
    const __half* A; __half* o16; int n0;
    if (y < split) { A = Ax; o16 = o16x; n0 = y * 96; }
    else           { A = Ar; o16 = o16r; n0 = (y - split + 1) * 96; }

    int m0 = blockIdx.x * 128;
    int t  = threadIdx.x;
    int warp = t >> 5, lane = t & 31;
    int wm = warp >> 1, wn = warp & 1;
    int g = lane >> 2, tg = lane & 3;

    unsigned as_base = sa(As), ws_base = sa(Ws);
    #pragma unroll
    for (int i = 0; i < 128 * CH / 256; i++) {
        int idx = t + i * 256;
        int m = idx / CH, c = idx % CH;
        cpa16(as_base + (unsigned)(m * AP + c * 4) * 4, A + (size_t)(m0 + m) * K + c * 8);
    }
    for (int idx = t; idx < 96 * CH; idx += 256) {
        int c = idx / CH, ck = idx % CH;
        cpa16(ws_base + (unsigned)(c * WPW + ck * 4) * 4, W + (size_t)(n0 + c) * K + ck * 8);
    }
    cpa_commit_wait();
    __syncthreads();

    float acc[2][6][4];
    #pragma unroll
    for (int i = 0; i < 2; i++)
        #pragma unroll
        for (int j = 0; j < 6; j++)
            #pragma unroll
            for (int q = 0; q < 4; q++) acc[i][j][q] = 0.0f;

    #pragma unroll
    for (int s = 0; s < K / 16; s++) {
        int kb = s * 8;
        unsigned a[2][4];
        #pragma unroll
        for (int i = 0; i < 2; i++) {
            int mb = (wm * 2 + i) * 16;
            a[i][0] = As[(mb + g)     * AP + kb + tg];
            a[i][1] = As[(mb + g + 8) * AP + kb + tg];
            a[i][2] = As[(mb + g)     * AP + kb + tg + 4];
            a[i][3] = As[(mb + g + 8) * AP + kb + tg + 4];
        }
        unsigned b[6][2];
        #pragma unroll
        for (int j = 0; j < 6; j++) {
            int col = wn * 48 + j * 8 + g;
            uint2 bv = *(const uint2*)&Ws[col * WPW + kb + 2 * tg];
            b[j][0] = bv.x;
            b[j][1] = bv.y;
        }
        #pragma unroll
        for (int i = 0; i < 2; i++)
            #pragma unroll
            for (int j = 0; j < 6; j++) mma_f16(acc[i][j], a[i], b[j]);
    }

    #pragma unroll
    for (int i = 0; i < 2; i++) {
        int rb = m0 + (wm * 2 + i) * 16;
        #pragma unroll
        for (int j = 0; j < 6; j++) {
            int c = wn * 48 + j * 8 + tg * 2;
            #pragma unroll
            for (int half = 0; half < 2; half++) {
                int row = rb + g + half * 8;
                float v0 = acc[i][j][half * 2]     + bias[n0 + c];
                float v1 = acc[i][j][half * 2 + 1] + bias[n0 + c + 1];
                if (ACT == 1) { v0 = gelu_f(v0); v1 = gelu_f(v1); }
                if (MODE == 1) {
                    int bb = row >> 16, rr = row & 65535, hy = rr >> 8, wx = rr & 255;
                    int tr = (bb << 16) | (((hy + 4) & 255) << 8) | ((wx + 4) & 255);
                    out32[(size_t)tr * 96 + c]     = res[(size_t)tr * 96 + c]     + v0;
                    out32[(size_t)tr * 96 + c + 1] = res[(size_t)tr * 96 + c + 1] + v1;
                } else if (MODE == 2) {
                    out32[(size_t)row * 96 + c]     = res[(size_t)row * 96 + c]     + v0;
                    out32[(size_t)row * 96 + c + 1] = res[(size_t)row * 96 + c + 1] + v1;
                } else {
                    *(__half2*)&o16[(size_t)row * outN + n0 + c] =
                        __floats2half2_rn(v0, v1);
                }
            }
        }
    }
}

// ---------------------------------------------------------------------------
// Tensor-core 3x3 SAME conv (implicit GEMM, fp16 m16n8k16), cp.async staging.
// Block: 16x16 px x 96 cout, 256 threads (8 warps: 4 Mquad x 2 Nhalf).
// Halo [324][20] natural; weights [9*96][24] ci-pair-permuted (LDS.64 B-frags).
// Smem 108,864 B => 2 CTAs/SM. grid = (16,16, b*(COUT/96)+cohalf).
// ---------------------------------------------------------------------------
template<int CIN, int COUT, int ACT, int RES, int O32, int O16>
__global__ void __launch_bounds__(256) conv_h(
        const __half* __restrict__ in16, const __half* __restrict__ w16t,
        const float* __restrict__ bias, const float* __restrict__ res,
        float* __restrict__ out32, __half* __restrict__ out16)
{
    constexpr int PIT = 20;           // halo kpair pitch (u32)
    constexpr int WP  = 24;           // weight kpair pitch (u32), LDS.64-safe
    constexpr int NH = COUT / 96;
    extern __shared__ unsigned smem_u[];
    unsigned* ws_u  = smem_u;                       // [9*96][WP]
    unsigned* ins_u = smem_u + 9 * 96 * WP;         // [324][PIT]

    int x0 = blockIdx.x * 16, y0 = blockIdx.y * 16;
    int zb = blockIdx.z;
    int cohalf = (NH == 1) ? 0 : (zb & 1);
    int b      = (NH == 1) ? zb : (zb >> 1);
    int t  = threadIdx.x;
    int warp = t >> 5, lane = t & 31;
    int wm = warp >> 1, wn = warp & 1;
    int g = lane >> 2, tg = lane & 3;

    unsigned ins_base = sa(ins_u), ws_base = sa(ws_u);

    float acc[4][6][4];
    #pragma unroll
    for (int i = 0; i < 4; i++)
        #pragma unroll
        for (int j = 0; j < 6; j++)
            #pragma unroll
            for (int q = 0; q < 4; q++) acc[i][j][q] = 0.0f;

    for (int ci0 = 0; ci0 < CIN; ci0 += 32) {
        // halo 18x18, 32 ci = 4 x 16B per pixel (natural layout)
        for (int idx = t; idx < 324 * 4; idx += 256) {
            int ck = idx & 3, pos = idx >> 2;
            int hp = pos / 18, wp = pos % 18;
            int gy = y0 + hp - 1, gx = x0 + wp - 1;
            unsigned dst = ins_base + (unsigned)(pos * PIT + ck * 4) * 4;
            if ((unsigned)gy < 256u && (unsigned)gx < 256u) {
                cpa16(dst, in16 + (size_t)((b << 16) | (gy << 8) | gx) * CIN + ci0 + ck * 8);
            } else {
                *(uint4*)&ins_u[pos * PIT + ck * 4] = make_uint4(0, 0, 0, 0);
            }
        }
        // weights: 9 taps x 96 co, 32 ci (permuted in mirror) = 4 x 16B per row
        for (int idx = t; idx < 9 * 96 * 4; idx += 256) {
            int ck = idx & 3, row = idx >> 2;       // row = tap*96 + co
            int tap = row / 96, co = row % 96;
            cpa16(ws_base + (unsigned)(row * WP + ck * 4) * 4,
                  w16t + ((size_t)tap * COUT + cohalf * 96 + co) * CIN + ci0 + ck * 8);
        }
        cpa_commit_wait();
        __syncthreads();

        #pragma unroll
        for (int dy = 0; dy < 3; dy++) {
            #pragma unroll
            for (int dx = 0; dx < 3; dx++) {
                const unsigned* wt = ws_u + (dy * 3 + dx) * 96 * WP;
                #pragma unroll
                for (int s = 0; s < 2; s++) {
                    int cb = s * 8;
                    unsigned a[4][4];
                    #pragma unroll
                    for (int i = 0; i < 4; i++) {
                        int base = (wm * 4 + i + dy) * 18 + dx;
                        a[i][0] = ins_u[(base + g)     * PIT + cb + tg];
                        a[i][1] = ins_u[(base + g + 8) * PIT + cb + tg];
                        a[i][2] = ins_u[(base + g)     * PIT + cb + tg + 4];
                        a[i][3] = ins_u[(base + g + 8) * PIT + cb + tg + 4];
                    }
                    unsigned bfr[6][2];
                    #pragma unroll
                    for (int j = 0; j < 6; j++) {
                        int col = wn * 48 + j * 8 + g;
                        uint2 bv = *(const uint2*)&wt[col * WP + cb + 2 * tg];
                        bfr[j][0] = bv.x;
                        bfr[j][1] = bv.y;
                    }
                    #pragma unroll
                    for (int i = 0; i < 4; i++)
                        #pragma unroll
                        for (int j = 0; j < 6; j++) mma_f16(acc[i][j], a[i], bfr[j]);
                }
            }
        }
        __syncthreads();
    }

    #pragma unroll
    for (int i = 0; i < 4; i++) {
        int y = y0 + wm * 4 + i;
        #pragma unroll
        for (int j = 0; j < 6; j++) {
            int co = cohalf * 96 + wn * 48 + j * 8 + tg * 2;
            float b0 = bias[co], b1 = bias[co + 1];
            #pragma unroll
            for (int half = 0; half < 2; half++) {
                int x = x0 + g + half * 8;
                size_t base = (size_t)((b << 16) | (y << 8) | x) * COUT + co;
                float v0 = acc[i][j][half * 2]     + b0;
                float v1 = acc[i][j][half * 2 + 1] + b1;
                if (ACT == 1) { v0 = fmaxf(v0, 0.0f); v1 = fmaxf(v1, 0.0f); }
                if (ACT == 2) { v0 = gelu_f(v0); v1 = gelu_f(v1); }
                if (RES) { v0 += res[base]; v1 += res[base + 1]; }
                if (O32) { out32[base] = v0; out32[base + 1] = v1; }
                if (O16) *(__half2*)&out16[base] = __floats2half2_rn(v0, v1);
            }
        }
    }
}

// ---------------------------------------------------------------------------
// Windowed dual attention. One block per (window, head-PAIR). 128 threads.
// ---------------------------------------------------------------------------
DEV int regio(int wblk, int i) { return (wblk < 31) ? 0 : ((i < 4) ? 1 : 2); }

DEV void attn_pass(const float4 (*K4)[4], const float4 (*V4)[4], const float4 q[4],
                   float lsv, const float* rpb_s, int i1, int j1, int cnt1,
                   int wh, int ww, float4 o[4])
{
    float s[64];
    #pragma unroll
    for (int m = 0; m < 64; m++) {
        const float4* kr = K4[m];
        float d;
        d  = q[0].x * kr[0].x + q[0].y * kr[0].y + q[0].z * kr[0].z + q[0].w * kr[0].w;
        d += q[1].x * kr[1].x + q[1].y * kr[1].y + q[1].z * kr[1].z + q[1].w * kr[1].w;
        d += q[2].x * kr[2].x + q[2].y * kr[2].y + q[2].z * kr[2].z + q[2].w * kr[2].w;
        d += q[3].x * kr[3].x + q[3].y * kr[3].y + q[3].z * kr[3].z + q[3].w * kr[3].w;
        int i2 = m >> 3, j2 = m & 7;
        float rb = rpb_s[(i1 - i2 + 7) * 15 + (j1 - j2 + 7)];
        int cnt2 = regio(wh, i2) * 3 + regio(ww, j2);
        s[m] = d * lsv + rb + ((cnt1 != cnt2) ? -100.0f : 0.0f);
    }
    float mx = s[0];
    #pragma unroll
    for (int m = 1; m < 64; m++) mx = fmaxf(mx, s[m]);
    float sum = 0.0f;
    float4 a0 = make_float4(0, 0, 0, 0), a1 = a0, a2 = a0, a3 = a0;
    #pragma unroll
    for (int m = 0; m < 64; m++) {
        float p = expf(s[m] - mx);
        sum += p;
        const float4* vr = V4[m];
        a0.x += p * vr[0].x; a0.y += p * vr[0].y; a0.z += p * vr[0].z; a0.w += p * vr[0].w;
        a1.x += p * vr[1].x; a1.y += p * vr[1].y; a1.z += p * vr[1].z; a1.w += p * vr[1].w;
        a2.x += p * vr[2].x; a2.y += p * vr[2].y; a2.z += p * vr[2].z; a2.w += p * vr[2].w;
        a3.x += p * vr[3].x; a3.y += p * vr[3].y; a3.z += p * vr[3].z; a3.w += p * vr[3].w;
    }
    float inv = 1.0f / sum;
    o[0] = make_float4(a0.x * inv, a0.y * inv, a0.z * inv, a0.w * inv);
    o[1] = make_float4(a1.x * inv, a1.y * inv, a1.z * inv, a1.w * inv);
    o[2] = make_float4(a2.x * inv, a2.y * inv, a2.z * inv, a2.w * inv);
    o[3] = make_float4(a3.x * inv, a3.y * inv, a3.z * inv, a3.w * inv);
}

__global__ void __launch_bounds__(128) attn_kernel(
        const __half* __restrict__ qkvx, const __half* __restrict__ qkvr,
        const float* __restrict__ lsp, const float* __restrict__ gat,
        const float* __restrict__ rpbt, float* __restrict__ out,
        __half* __restrict__ out16)
{
    __shared__ float4 ks[2][64][4], vs[2][64][4], krs[2][64][4], vrs[2][64][4];
    __shared__ float rpb_s[2][225];
    int blk  = blockIdx.x;
    int hp   = blk % (HEADS / 2);
    int widx = blk / (HEADS / 2);
    int b  = widx >> 10;
    int nw = widx & 1023;
    int wh = nw >> 5, ww = nw & 31;
    int t  = threadIdx.x;
    int hl = t >> 6;
    int n  = t & 63;
    int head = hp * 2 + hl;
    int i1 = n >> 3, j1 = n & 7;

    size_t tok = (size_t)((b << 16) | ((wh * 8 + i1) << 8) | (ww * 8 + j1));
    size_t rowbase = tok * 288 + head * 16;

    float4 q[4];
    {
        ldh16(qkvx + rowbase, q);
        float ss = 0.0f;
        #pragma unroll
        for (int i = 0; i < 4; i++)
            ss += q[i].x * q[i].x + q[i].y * q[i].y + q[i].z * q[i].z + q[i].w * q[i].w;
        float inv = 1.0f / fmaxf(sqrtf(ss), 1e-12f);
        #pragma unroll
        for (int i = 0; i < 4; i++) { q[i].x *= inv; q[i].y *= inv; q[i].z *= inv; q[i].w *= inv; }
    }
    {
        float4 kv[4];
        ldh16(qkvx + rowbase + 96, kv);
        float ss = 0.0f;
        #pragma unroll
        for (int i = 0; i < 4; i++)
            ss += kv[i].x * kv[i].x + kv[i].y * kv[i].y + kv[i].z * kv[i].z + kv[i].w * kv[i].w;
        float inv = 1.0f / fmaxf(sqrtf(ss), 1e-12f);
        #pragma unroll
        for (int i = 0; i < 4; i++)
            ks[hl][n][i] = make_float4(kv[i].x * inv, kv[i].y * inv, kv[i].z * inv, kv[i].w * inv);
        float4 vv[4];
        ldh16(qkvx + rowbase + 192, vv);
        #pragma unroll
        for (int i = 0; i < 4; i++) vs[hl][n][i] = vv[i];
    }
    {
        float4 kv[4];
        ldh16(qkvr + rowbase + 96, kv);
        float ss = 0.0f;
        #pragma unroll
        for (int i = 0; i < 4; i++)
            ss += kv[i].x * kv[i].x + kv[i].y * kv[i].y + kv[i].z * kv[i].z + kv[i].w * kv[i].w;
        float inv = 1.0f / fmaxf(sqrtf(ss), 1e-12f);
        #pragma unroll
        for (int i = 0; i < 4; i++)
            krs[hl][n][i] = make_float4(kv[i].x * inv, kv[i].y * inv, kv[i].z * inv, kv[i].w * inv);
        float4 vv[4];
        ldh16(qkvr + rowbase + 192, vv);
        #pragma unroll
        for (int i = 0; i < 4; i++) vrs[hl][n][i] = vv[i];
    }
    for (int idx = n; idx < 225; idx += 64) rpb_s[hl][idx] = rpbt[idx * 6 + head];

    float lsv = expf(fminf(lsp[head], 4.605170185988092f));
    float gv  = 1.0f / (1.0f + expf(-gat[head]));
    int cnt1 = regio(wh, i1) * 3 + regio(ww, j1);
    __syncthreads();

    float4 o1[4], o2[4];
    attn_pass(ks[hl],  vs[hl],  q, lsv, rpb_s[hl], i1, j1, cnt1, wh, ww, o1);
    attn_pass(krs[hl], vrs[hl], q, lsv, rpb_s[hl], i1, j1, cnt1, wh, ww, o2);

    float4* op = (float4*)(out + tok * 96 + head * 16);
    __half2* oh = (__half2*)(out16 + tok * 96 + head * 16);
    float og = 1.0f - gv;
    #pragma unroll
    for (int i = 0; i < 4; i++) {
        float4 v = make_float4(og * o1[i].x + gv * o2[i].x,
                               og * o1[i].y + gv * o2[i].y,
                               og * o1[i].z + gv * o2[i].z,
                               og * o1[i].w + gv * o2[i].w);
        op[i] = v;
        oh[2 * i]     = __floats2half2_rn(v.x, v.y);
        oh[2 * i + 1] = __floats2half2_rn(v.z, v.w);
    }
}

// ---------------------------------------------------------------------------
// Host orchestration
// ---------------------------------------------------------------------------
static int g_attr_done = 0;

extern "C" void kernel_launch(void* const* d_in, const int* in_sizes, int n_in,
                              void* d_out, int out_size)
{
    const float* x       = (const float*)d_in[0];
    const float* ref     = (const float*)d_in[1];
    const float* n1g     = (const float*)d_in[2];
    const float* n1b     = (const float*)d_in[3];
    const float* qkv_w   = (const float*)d_in[4];
    const float* qkv_b   = (const float*)d_in[5];
    const float* lscale  = (const float*)d_in[6];
    const float* gating  = (const float*)d_in[7];
    const float* rpbt    = (const float*)d_in[8];
    const float* trunk_w = (const float*)d_in[9];
    const float* trunk_b = (const float*)d_in[10];
    const float* proj_w  = (const float*)d_in[11];
    const float* proj_b  = (const float*)d_in[12];
    const float* n2g     = (const float*)d_in[13];
    const float* n2b     = (const float*)d_in[14];
    const float* fc1_w   = (const float*)d_in[15];
    const float* fc1_b   = (const float*)d_in[16];
    const float* convm_w = (const float*)d_in[17];
    const float* convm_b = (const float*)d_in[18];
    const float* fc2_w   = (const float*)d_in[19];
    const float* fc2_b   = (const float*)d_in[20];
    float* out = (float*)d_out;

    float *ybuf, *x2;
    __half *qkvx16, *qkvr16, *ln16, *lnr16, *y16, *t16, *h16, *h16b;
    __half *qkvw16, *projw16, *fc1w16, *fc2w16, *trunkw16, *convmw16;
    cudaGetSymbolAddress((void**)&ybuf, g_y);
    cudaGetSymbolAddress((void**)&x2,   g_x2);
    cudaGetSymbolAddress((void**)&qkvx16, g_qkvx16);
    cudaGetSymbolAddress((void**)&qkvr16, g_qkvr16);
    cudaGetSymbolAddress((void**)&ln16, g_ln16);
    cudaGetSymbolAddress((void**)&lnr16,g_lnr16);
    cudaGetSymbolAddress((void**)&y16,  g_y16);
    cudaGetSymbolAddress((void**)&t16,  g_t16);
    cudaGetSymbolAddress((void**)&h16,  g_h16);
    cudaGetSymbolAddress((void**)&h16b, g_h16b);
    cudaGetSymbolAddress((void**)&qkvw16,  g_qkvw16);
    cudaGetSymbolAddress((void**)&projw16, g_projw16);
    cudaGetSymbolAddress((void**)&fc1w16,  g_fc1w16);
    cudaGetSymbolAddress((void**)&fc2w16,  g_fc2w16);
    cudaGetSymbolAddress((void**)&trunkw16,g_trunkw16);
    cudaGetSymbolAddress((void**)&convmw16,g_convmw16);

    const int CONV_SMEM    = (9 * 96 * 24 + 324 * 20) * 4;   // 108864
    const int GEMM_SMEM96  = (128 * 52 + 96 * 56) * 4;       // 48128
    const int GEMM_SMEM192 = (128 * 100 + 96 * 104) * 4;     // 91136

    if (!g_attr_done) {
        cudaFuncSetAttribute(conv_h<96, 96, 1, 0, 0, 1>,   cudaFuncAttributeMaxDynamicSharedMemorySize, CONV_SMEM);
        cudaFuncSetAttribute(conv_h<96, 96, 0, 1, 1, 1>,   cudaFuncAttributeMaxDynamicSharedMemorySize, CONV_SMEM);
        cudaFuncSetAttribute(conv_h<192, 192, 2, 0, 0, 1>, cudaFuncAttributeMaxDynamicSharedMemorySize, CONV_SMEM);
        cudaFuncSetAttribute(gemm_h<96, 0, 3>,  cudaFuncAttributeMaxDynamicSharedMemorySize, GEMM_SMEM96);
        cudaFuncSetAttribute(gemm_h<96, 1, 3>,  cudaFuncAttributeMaxDynamicSharedMemorySize, GEMM_SMEM96);
        cudaFuncSetAttribute(gemm_h<96, 0, 1>,  cudaFuncAttributeMaxDynamicSharedMemorySize, GEMM_SMEM96);
        cudaFuncSetAttribute(gemm_h<192, 0, 2>, cudaFuncAttributeMaxDynamicSharedMemorySize, GEMM_SMEM192);
        g_attr_done = 1;
    }

    // 1-2: conversions (trunk weights before conv1; qkv weights before gemm)
    tohalfTp_k<<<(36 * 96 * 96 + 255) / 256, 256>>>(trunk_w, trunkw16, 96, 96, 36);
    tohalfp_k<<<(288 * 96 + 255) / 256, 256>>>(qkv_w, qkvw16, 288 * 96, 96);

    // 3: fused LN1 (x and ref), roll(-4,-4)
    ln2_kernel<<<2 * (TOK / 8), 256>>>(x, ref, n1g, n1b, ln16, lnr16);

    // 4: fused qkv (groups 0-2: x; 3-4: ref k,v)
    gemm_h<96, 0, 3><<<dim3(TOK / 128, 5), 256, GEMM_SMEM96>>>(
        ln16, lnr16, qkvw16, qkv_b, nullptr, nullptr, qkvx16, qkvr16, 288, 3);

    // 5: attention (2 heads per block)
    attn_kernel<<<Bb * 1024 * (HEADS / 2), 128>>>(qkvx16, qkvr16, lscale, gating, rpbt, ybuf, y16);

    // 6-9: trunk convs
    conv_h<96, 96, 1, 0, 0, 1><<<dim3(16, 16, Bb), 256, CONV_SMEM>>>(y16, trunkw16,              trunk_b,       nullptr, nullptr, t16);
    conv_h<96, 96, 0, 1, 1, 1><<<dim3(16, 16, Bb), 256, CONV_SMEM>>>(t16, trunkw16 + 1 * 82944, trunk_b + 96,  ybuf, ybuf, y16);
    conv_h<96, 96, 1, 0, 0, 1><<<dim3(16, 16, Bb), 256, CONV_SMEM>>>(y16, trunkw16 + 2 * 82944, trunk_b + 192, nullptr, nullptr, t16);
    conv_h<96, 96, 0, 1, 1, 1><<<dim3(16, 16, Bb), 256, CONV_SMEM>>>(t16, trunkw16 + 3 * 82944, trunk_b + 288, ybuf, ybuf, y16);

    // 10-11: proj + roll back + residual
    tohalfp_k<<<(96 * 96 + 255) / 256, 256>>>(proj_w, projw16, 96 * 96, 96);
    gemm_h<96, 0, 1><<<dim3(TOK / 128, 1), 256, GEMM_SMEM96>>>(
        y16, y16, projw16, proj_b, x, x2, nullptr, nullptr, 96, 99);

    // 12-14: LN2 + fc1 (gelu)
    ln_kernel<<<TOK / 8, 256>>>(x2, n2g, n2b, t16, 0);
    tohalfp_k<<<(192 * 96 + 255) / 256, 256>>>(fc1_w, fc1w16, 192 * 96, 96);
    gemm_h<96, 1, 3><<<dim3(TOK / 128, 2), 256, GEMM_SMEM96>>>(
        t16, t16, fc1w16, fc1_b, nullptr, nullptr, h16, h16, 192, 99);

    // 15-16: convm
    tohalfTp_k<<<(9 * 192 * 192 + 255) / 256, 256>>>(convm_w, convmw16, 192, 192, 9);
    conv_h<192, 192, 2, 0, 0, 1><<<dim3(16, 16, Bb * 2), 256, CONV_SMEM>>>(h16, convmw16, convm_b, nullptr, nullptr, h16b);

    // 17-18: fc2 + residual -> out
    tohalfp_k<<<(96 * 192 + 255) / 256, 256>>>(fc2_w, fc2w16, 96 * 192, 192);
    gemm_h<192, 0, 2><<<dim3(TOK / 128, 1), 256, GEMM_SMEM192>>>(
        h16b, h16b, fc2w16, fc2_b, x2, out, nullptr, nullptr, 96, 99);
}